// round 13
// baseline (speedup 1.0000x reference)
#include <cuda_runtime.h>
#include <cuda_bf16.h>
#include <math.h>
#include <stdint.h>

// ---------------------------------------------------------------------------
// Scratch (__device__ globals; no allocations allowed)
// ---------------------------------------------------------------------------
#define MAXROI 2048
#define K1MAX  12544

__device__ __nv_bfloat16 g_w1t_hi[3u * 1024u * K1MAX];
__device__ __nv_bfloat16 g_w1t_lo[3u * 1024u * K1MAX];
__device__ __nv_bfloat16 g_w2t_hi[3u * 1024u * 1024u];
__device__ __nv_bfloat16 g_w2t_lo[3u * 1024u * 1024u];
__device__ __nv_bfloat16 g_pool_hi[MAXROI * K1MAX];
__device__ __nv_bfloat16 g_pool_lo[MAXROI * K1MAX];
__device__ __nv_bfloat16 g_h1_hi[3u * MAXROI * 1024u];
__device__ __nv_bfloat16 g_h1_lo[3u * MAXROI * 1024u];
__device__ float g_h2[3u * MAXROI * 1024u];
__device__ float g_logits[3 * MAXROI * 81];
__device__ float g_deltas[MAXROI * 4];
__device__ float g_rois[MAXROI * 4];

// ---------------------------------------------------------------------------
// PTX helpers (baseline compute_103-legal instructions only)
// ---------------------------------------------------------------------------
__device__ __forceinline__ uint32_t smem_u32(const void* p) {
    uint32_t a;
    asm("{ .reg .u64 t; cvta.to.shared.u64 t, %1; cvt.u32.u64 %0, t; }" : "=r"(a) : "l"(p));
    return a;
}

#define CP_ASYNC16(dst, src) \
    asm volatile("cp.async.cg.shared.global [%0], [%1], 16;" :: "r"(dst), "l"(src) : "memory")
#define CP_ASYNC16_Z(dst, src, sz) \
    asm volatile("cp.async.cg.shared.global [%0], [%1], 16, %2;" :: "r"(dst), "l"(src), "r"(sz) : "memory")
#define CP_COMMIT()  asm volatile("cp.async.commit_group;" ::: "memory")
#define CP_WAIT1()   asm volatile("cp.async.wait_group 1;" ::: "memory")

#define LDSM_X4(r, addr) \
    asm volatile("ldmatrix.sync.aligned.m8n8.x4.shared.b16 {%0,%1,%2,%3}, [%4];" \
        : "=r"((r)[0]), "=r"((r)[1]), "=r"((r)[2]), "=r"((r)[3]) : "r"(addr))

#define MMA16816(d, a, b) \
    asm volatile("mma.sync.aligned.m16n8k16.row.col.f32.bf16.bf16.f32 " \
        "{%0,%1,%2,%3}, {%4,%5,%6,%7}, {%8,%9}, {%0,%1,%2,%3};" \
        : "+f"((d)[0]), "+f"((d)[1]), "+f"((d)[2]), "+f"((d)[3]) \
        : "r"((a)[0]), "r"((a)[1]), "r"((a)[2]), "r"((a)[3]), "r"((b)[0]), "r"((b)[1]))

// ---------------------------------------------------------------------------
// Copy rois
// ---------------------------------------------------------------------------
__global__ void copy_rois_kernel(const float* __restrict__ src, float* __restrict__ dst, int n4) {
    int i = blockIdx.x * blockDim.x + threadIdx.x;
    if (i < n4) dst[i] = src[i];
}

// ---------------------------------------------------------------------------
// Weight transpose + bf16 split:  W[K,N] fp32  ->  WT_hi/lo [N,K] bf16
// ---------------------------------------------------------------------------
__global__ void wsplitT_kernel(const float* __restrict__ W,
                               __nv_bfloat16* __restrict__ Thi,
                               __nv_bfloat16* __restrict__ Tlo, int K, int N) {
    __shared__ float t[32][33];
    const int h = blockIdx.z;
    const float* Wp = W + (size_t)h * K * N;
    __nv_bfloat16* Hp = Thi + (size_t)h * N * K;
    __nv_bfloat16* Lp = Tlo + (size_t)h * N * K;
    const int k0 = blockIdx.x * 32, n0 = blockIdx.y * 32;
    const int tx = threadIdx.x, ty = threadIdx.y;
#pragma unroll
    for (int r = 0; r < 32; r += 8)
        t[ty + r][tx] = Wp[(size_t)(k0 + ty + r) * N + n0 + tx];
    __syncthreads();
#pragma unroll
    for (int r = 0; r < 32; r += 8) {
        float v = t[tx][ty + r];
        __nv_bfloat16 hi = __float2bfloat16(v);
        float lo = v - __bfloat162float(hi);
        size_t o = (size_t)(n0 + ty + r) * K + k0 + tx;
        Hp[o] = hi;
        Lp[o] = __float2bfloat16(lo);
    }
}

// ---------------------------------------------------------------------------
// Pyramid ROI align -> bf16 hi/lo.  grid (49, nroi), block 256.
// Lane 0 computes the per-(roi,pixel) scalar math once -> smem broadcast;
// all 256 threads then do just 4 gathers + 7 FMA + 2 stores.
// ---------------------------------------------------------------------------
__global__ void roi_align_kernel(
    const float* __restrict__ P2, const float* __restrict__ P3,
    const float* __restrict__ P4, const float* __restrict__ P5,
    int H2, int H3, int H4, int H5,
    const float* __restrict__ rois,
    __nv_bfloat16* __restrict__ phi, __nv_bfloat16* __restrict__ plo)
{
    __shared__ int   s_lvl;
    __shared__ int   s_o[4];
    __shared__ float s_w[4];

    const int n  = blockIdx.y;
    const int pp = blockIdx.x;

    if (threadIdx.x == 0) {
        const int py = pp / 7, px = pp % 7;
        const float y1 = rois[n * 4 + 0];
        const float x1 = rois[n * 4 + 1];
        const float y2 = rois[n * 4 + 2];
        const float x2 = rois[n * 4 + 3];
        const float hh = y2 - y1, ww = x2 - x1;

        float hwv = fmaxf(hh * ww, 1e-6f);
        float lf  = floorf(4.0f + log2f(sqrtf(hwv) / 224.0f));
        lf = fminf(fmaxf(lf, 2.0f), 5.0f);
        const int li = (int)lf - 2;

        int H;
        float stride;
        switch (li) {
            case 0:  H = H2; stride = 4.0f;  break;
            case 1:  H = H3; stride = 8.0f;  break;
            case 2:  H = H4; stride = 16.0f; break;
            default: H = H5; stride = 32.0f; break;
        }

        const float s0 = y1 / stride, s1 = x1 / stride;
        const float s2 = y2 / stride, s3 = x2 / stride;
        const float gy = ((float)py + 0.5f) / 7.0f;
        const float gx = ((float)px + 0.5f) / 7.0f;
        const float ys = __fadd_rn(s0, __fmul_rn(gy, __fsub_rn(s2, s0)));
        const float xs = __fadd_rn(s1, __fmul_rn(gx, __fsub_rn(s3, s1)));

        const float Hm1 = (float)(H - 1);
        const float y0f = fminf(fmaxf(floorf(ys), 0.0f), Hm1);
        const float x0f = fminf(fmaxf(floorf(xs), 0.0f), Hm1);
        const int y0 = (int)y0f, x0 = (int)x0f;
        const int y1i = min(y0 + 1, H - 1);
        const int x1i = min(x0 + 1, H - 1);
        const float wy = fminf(fmaxf(ys - y0f, 0.0f), 1.0f);
        const float wx = fminf(fmaxf(xs - x0f, 0.0f), 1.0f);
        const float omwy = 1.0f - wy, omwx = 1.0f - wx;

        s_lvl  = li;
        s_o[0] = (y0  * H + x0 ) * 256;
        s_o[1] = (y0  * H + x1i) * 256;
        s_o[2] = (y1i * H + x0 ) * 256;
        s_o[3] = (y1i * H + x1i) * 256;
        s_w[0] = omwy * omwx;
        s_w[1] = omwy * wx;
        s_w[2] = wy * omwx;
        s_w[3] = wy * wx;
    }
    __syncthreads();

    const float* feat;
    switch (s_lvl) {
        case 0:  feat = P2; break;
        case 1:  feat = P3; break;
        case 2:  feat = P4; break;
        default: feat = P5; break;
    }

    const int c = threadIdx.x;
    float r = feat[s_o[0] + c] * s_w[0];
    r = r + feat[s_o[1] + c] * s_w[1];
    r = r + feat[s_o[2] + c] * s_w[2];
    r = r + feat[s_o[3] + c] * s_w[3];

    const size_t idx = ((size_t)n * 49 + pp) * 256 + c;
    __nv_bfloat16 hi = __float2bfloat16(r);
    phi[idx] = hi;
    plo[idx] = __float2bfloat16(r - __bfloat162float(hi));
}

// ---------------------------------------------------------------------------
// mma.sync split-bf16 GEMM.  Logical output width is always 1024:
//   B has NB rows (NB = 1024, or 3072 for head-batched fc1); output column
//   colg maps to (head = colg>>10, col = colg&1023), written at
//   head*M*1024 + row*1024 + col.  blockIdx.z offsets A/B/bias/C by z-strides.
// D += AhiBhi + AhiBlo + AloBhi (fp32 accum, ~2^-16).
// CTA tile 128x64, BK=32, 8 warps, 3-stage cp.async, 1 syncthreads/iter.
// ---------------------------------------------------------------------------
__global__ __launch_bounds__(256) void gemm_mma_kernel(
    const __nv_bfloat16* __restrict__ Ahi, const __nv_bfloat16* __restrict__ Alo,
    const __nv_bfloat16* __restrict__ Bhi, const __nv_bfloat16* __restrict__ Blo,
    const float* __restrict__ bias,
    float* __restrict__ Cf, __nv_bfloat16* __restrict__ Chi, __nv_bfloat16* __restrict__ Clo,
    int M, int K, int doRelu,
    long zA, long zB, long zBias, long zC)
{
    extern __shared__ char smem[];
    const uint32_t sb = smem_u32(smem);

    const int z = blockIdx.z;
    Ahi += (size_t)zA * z;  Alo += (size_t)zA * z;
    Bhi += (size_t)zB * z;  Blo += (size_t)zB * z;
    bias += (size_t)zBias * z;
    if (Cf)  Cf  += (size_t)zC * z;
    if (Chi) { Chi += (size_t)zC * z; Clo += (size_t)zC * z; }

    const int tid  = threadIdx.x;
    const int lane = tid & 31, warp = tid >> 5;
    const int warpM = warp & 3, warpN = warp >> 2;
    const int wm0 = warpM * 32, wn0 = warpN * 32;
    const int bm0 = blockIdx.y * 128, bn0 = blockIdx.x * 64;

    const uint32_t STAGE = 30720u;   // Ahi 10240 | Alo 10240 | Bhi 5120 | Blo 5120

    float acc[2][4][4];
#pragma unroll
    for (int mt = 0; mt < 2; mt++)
#pragma unroll
        for (int nt = 0; nt < 4; nt++)
#pragma unroll
            for (int i = 0; i < 4; i++) acc[mt][nt][i] = 0.0f;

    auto load_stage = [&](int s, int kc) {
        const int k0 = kc * 32;
        const uint32_t base = sb + (uint32_t)s * STAGE;
#pragma unroll
        for (int it = 0; it < 2; it++) {
            const int i   = tid + it * 256;
            const int row = i >> 2, cj = i & 3;
            const uint32_t d  = base + (uint32_t)row * 80u + (uint32_t)cj * 16u;
            const int gr = bm0 + row;
            const int sz = (gr < M) ? 16 : 0;
            const size_t go = (size_t)gr * K + k0 + cj * 8;
            CP_ASYNC16_Z(d,           Ahi + go, sz);
            CP_ASYNC16_Z(d + 10240u,  Alo + go, sz);
        }
        {
            const int row = tid >> 2, cj = tid & 3;
            const uint32_t d = base + 20480u + (uint32_t)row * 80u + (uint32_t)cj * 16u;
            const size_t go = (size_t)(bn0 + row) * K + k0 + cj * 8;
            CP_ASYNC16(d,          Bhi + go);
            CP_ASYNC16(d + 5120u,  Blo + go);
        }
        CP_COMMIT();
    };

    const uint32_t aRow = (uint32_t)(wm0 + (lane & 15));
    const uint32_t aCol = (uint32_t)((lane >> 4) * 16);
    const uint32_t bRow = (uint32_t)(wn0 + ((lane >> 4) & 1) * 8 + (lane & 7));
    const uint32_t bCol = (uint32_t)(((lane >> 3) & 1) * 16);

    auto load_frag = [&](uint32_t base, int ks,
                         uint32_t (&a_h)[2][4], uint32_t (&a_l)[2][4],
                         uint32_t (&b_h)[4][2], uint32_t (&b_l)[4][2]) {
#pragma unroll
        for (int mt = 0; mt < 2; mt++) {
            const uint32_t ad = base + (aRow + (uint32_t)mt * 16u) * 80u + aCol + (uint32_t)ks * 32u;
            LDSM_X4(a_h[mt], ad);
            LDSM_X4(a_l[mt], ad + 10240u);
        }
#pragma unroll
        for (int p = 0; p < 2; p++) {
            const uint32_t bd = base + 20480u + (bRow + (uint32_t)p * 16u) * 80u + bCol + (uint32_t)ks * 32u;
            uint32_t r[4];
            LDSM_X4(r, bd);
            b_h[2*p][0] = r[0]; b_h[2*p][1] = r[1];
            b_h[2*p+1][0] = r[2]; b_h[2*p+1][1] = r[3];
            LDSM_X4(r, bd + 5120u);
            b_l[2*p][0] = r[0]; b_l[2*p][1] = r[1];
            b_l[2*p+1][0] = r[2]; b_l[2*p+1][1] = r[3];
        }
    };

    auto run_mma = [&](uint32_t (&a_h)[2][4], uint32_t (&a_l)[2][4],
                       uint32_t (&b_h)[4][2], uint32_t (&b_l)[4][2]) {
#pragma unroll
        for (int mt = 0; mt < 2; mt++)
#pragma unroll
            for (int nt = 0; nt < 4; nt++) {
                MMA16816(acc[mt][nt], a_h[mt], b_h[nt]);
                MMA16816(acc[mt][nt], a_h[mt], b_l[nt]);
                MMA16816(acc[mt][nt], a_l[mt], b_h[nt]);
            }
    };

    const int nkc = K >> 5;          // K >= 1024 always here
    load_stage(0, 0);
    load_stage(1, 1);

    for (int kc = 0; kc < nkc; kc++) {
        CP_WAIT1();
        __syncthreads();
        if (kc + 2 < nkc) load_stage((kc + 2) % 3, kc + 2);

        const uint32_t base = sb + (uint32_t)(kc % 3) * STAGE;
        uint32_t a_h0[2][4], a_l0[2][4], b_h0[4][2], b_l0[4][2];
        uint32_t a_h1[2][4], a_l1[2][4], b_h1[4][2], b_l1[4][2];
        load_frag(base, 0, a_h0, a_l0, b_h0, b_l0);
        load_frag(base, 1, a_h1, a_l1, b_h1, b_l1);
        run_mma(a_h0, a_l0, b_h0, b_l0);
        run_mma(a_h1, a_l1, b_h1, b_l1);
    }

    // epilogue with head-aware column mapping (logical out width 1024)
    const int erow = lane >> 2;
    const int ecol = (lane & 3) * 2;
#pragma unroll
    for (int mt = 0; mt < 2; mt++)
#pragma unroll
        for (int nt = 0; nt < 4; nt++) {
            const int colg = bn0 + wn0 + nt * 8 + ecol;
            const int head = colg >> 10;
            const int col  = colg & 1023;
            const float b0v = bias[colg], b1v = bias[colg + 1];
            const size_t hbase = (size_t)head * M * 1024;
#pragma unroll
            for (int h = 0; h < 2; h++) {
                const int row = bm0 + wm0 + mt * 16 + erow + h * 8;
                if (row >= M) continue;
                float v0 = acc[mt][nt][h * 2 + 0] + b0v;
                float v1 = acc[mt][nt][h * 2 + 1] + b1v;
                if (doRelu) { v0 = fmaxf(v0, 0.0f); v1 = fmaxf(v1, 0.0f); }
                const size_t o = hbase + (size_t)row * 1024 + col;
                if (Cf) { Cf[o] = v0; Cf[o + 1] = v1; }
                if (Chi) {
                    __nv_bfloat16 h0 = __float2bfloat16(v0);
                    __nv_bfloat16 h1 = __float2bfloat16(v1);
                    Chi[o]     = h0;
                    Chi[o + 1] = h1;
                    Clo[o]     = __float2bfloat16(v0 - __bfloat162float(h0));
                    Clo[o + 1] = __float2bfloat16(v1 - __bfloat162float(h1));
                }
            }
        }
}

// ---------------------------------------------------------------------------
// Small-N GEMM (cls N=81, reg N=4), warp-per-column shuffle reduction.
// grid (M, nz), block 256.  z-strides select the head.
// ---------------------------------------------------------------------------
__global__ __launch_bounds__(256) void gemm_small_kernel(
    const float* __restrict__ A, const float* __restrict__ W,
    const float* __restrict__ bias, float* __restrict__ C, int N, int K,
    long zA, long zW, long zBias, long zC)
{
    __shared__ float a[1024];
    const int z = blockIdx.y;
    A += (size_t)zA * z;  W += (size_t)zW * z;
    bias += (size_t)zBias * z;  C += (size_t)zC * z;

    const int row = blockIdx.x;
    const int tid = threadIdx.x, lane = tid & 31, warp = tid >> 5;
    for (int k = tid; k < K; k += 256)
        a[k] = A[(size_t)row * K + k];
    __syncthreads();

    for (int col = warp; col < N; col += 8) {
        float s = 0.0f;
        for (int k = lane; k < K; k += 32)
            s += a[k] * W[(size_t)k * N + col];
#pragma unroll
        for (int off = 16; off > 0; off >>= 1)
            s += __shfl_xor_sync(0xFFFFFFFFu, s, off);
        if (lane == 0)
            C[(size_t)row * N + col] = s + bias[col];
    }
}

// ---------------------------------------------------------------------------
// delta2bbox (in-place)
// ---------------------------------------------------------------------------
__global__ void delta2bbox_kernel(float* __restrict__ rois,
                                  const float* __restrict__ deltas, int nroi)
{
    int n = blockIdx.x * blockDim.x + threadIdx.x;
    if (n >= nroi) return;
    const float y1 = rois[n * 4 + 0];
    const float x1 = rois[n * 4 + 1];
    const float y2 = rois[n * 4 + 2];
    const float x2 = rois[n * 4 + 3];
    const float d0 = deltas[n * 4 + 0] * 0.1f;
    const float d1 = deltas[n * 4 + 1] * 0.1f;
    const float d2 = deltas[n * 4 + 2] * 0.2f;
    const float d3 = deltas[n * 4 + 3] * 0.2f;
    float h = y2 - y1;
    float w = x2 - x1;
    const float cy = y1 + 0.5f * h + d0 * h;
    const float cx = x1 + 0.5f * w + d1 * w;
    h = h * expf(d2);
    w = w * expf(d3);
    rois[n * 4 + 0] = fminf(fmaxf(cy - 0.5f * h, 0.0f), 1024.0f);
    rois[n * 4 + 1] = fminf(fmaxf(cx - 0.5f * w, 0.0f), 1024.0f);
    rois[n * 4 + 2] = fminf(fmaxf(cy + 0.5f * h, 0.0f), 1024.0f);
    rois[n * 4 + 3] = fminf(fmaxf(cx + 0.5f * w, 0.0f), 1024.0f);
}

// ---------------------------------------------------------------------------
// 3-head softmax average
// ---------------------------------------------------------------------------
__global__ __launch_bounds__(128) void softmax_avg_kernel(
    const float* __restrict__ logits, float* __restrict__ out, int nroi)
{
    __shared__ float red[128];
    const int n = blockIdx.x;
    const int c = threadIdx.x;
    float acc = 0.0f;

    for (int h = 0; h < 3; h++) {
        float v = (c < 81) ? logits[(size_t)h * nroi * 81 + (size_t)n * 81 + c] : -3.0e38f;
        red[c] = v;
        __syncthreads();
#pragma unroll
        for (int s = 64; s > 0; s >>= 1) {
            if (c < s) red[c] = fmaxf(red[c], red[c + s]);
            __syncthreads();
        }
        const float m = red[0];
        __syncthreads();
        const float e = (c < 81) ? expf(v - m) : 0.0f;
        red[c] = e;
        __syncthreads();
#pragma unroll
        for (int s = 64; s > 0; s >>= 1) {
            if (c < s) red[c] += red[c + s];
            __syncthreads();
        }
        const float ssum = red[0];
        __syncthreads();
        acc += e / ssum;
    }
    if (c < 81) out[(size_t)n * 81 + c] = acc / 3.0f;
}

// ---------------------------------------------------------------------------
// Launcher
// ---------------------------------------------------------------------------
extern "C" void kernel_launch(void* const* d_in, const int* in_sizes, int n_in,
                              void* d_out, int out_size)
{
    const float* P2    = (const float*)d_in[0];
    const float* P3    = (const float*)d_in[1];
    const float* P4    = (const float*)d_in[2];
    const float* P5    = (const float*)d_in[3];
    const float* rois  = (const float*)d_in[4];
    const float* fc1_w = (const float*)d_in[5];
    const float* fc1_b = (const float*)d_in[6];
    const float* fc2_w = (const float*)d_in[7];
    const float* fc2_b = (const float*)d_in[8];
    const float* cls_w = (const float*)d_in[9];
    const float* cls_b = (const float*)d_in[10];
    const float* reg_w = (const float*)d_in[11];
    const float* reg_b = (const float*)d_in[12];
    float* out = (float*)d_out;

    const int nroi = in_sizes[4] / 4;
    if (nroi <= 0 || nroi > MAXROI) return;

    int H[4];
    for (int i = 0; i < 4; i++) {
        double e = (double)in_sizes[i] / 256.0;
        H[i] = (int)(sqrt(e) + 0.5);
    }
    const int K1 = in_sizes[5] / (3 * 1024);   // 12544
    if (K1 > K1MAX || (K1 & 31)) return;

    __nv_bfloat16 *w1h, *w1l, *w2h, *w2l, *ph, *pl, *h1h, *h1l;
    float *h2_p, *logits_p, *deltas_p, *rois_p;
    cudaGetSymbolAddress((void**)&w1h, g_w1t_hi);
    cudaGetSymbolAddress((void**)&w1l, g_w1t_lo);
    cudaGetSymbolAddress((void**)&w2h, g_w2t_hi);
    cudaGetSymbolAddress((void**)&w2l, g_w2t_lo);
    cudaGetSymbolAddress((void**)&ph,  g_pool_hi);
    cudaGetSymbolAddress((void**)&pl,  g_pool_lo);
    cudaGetSymbolAddress((void**)&h1h, g_h1_hi);
    cudaGetSymbolAddress((void**)&h1l, g_h1_lo);
    cudaGetSymbolAddress((void**)&h2_p,     g_h2);
    cudaGetSymbolAddress((void**)&logits_p, g_logits);
    cudaGetSymbolAddress((void**)&deltas_p, g_deltas);
    cudaGetSymbolAddress((void**)&rois_p,   g_rois);

    const int GEMM_SMEM = 3 * 30720;   // 92160 B
    cudaFuncSetAttribute(gemm_mma_kernel, cudaFuncAttributeMaxDynamicSharedMemorySize, GEMM_SMEM);

    const dim3 alignGrid(49, nroi);
    const int mTiles = (nroi + 127) / 128;
    const int cpBlocks = (nroi * 4 + 255) / 256;
    const int dbBlocks = (nroi + 255) / 256;
    const size_t w1hd = (size_t)1024 * K1;
    const size_t w2hd = (size_t)1024 * 1024;
    const long mslab = (long)nroi * 1024;

    copy_rois_kernel<<<cpBlocks, 256>>>(rois, rois_p, nroi * 4);

    // weight transpose + split
    {
        dim3 g1(K1 / 32, 1024 / 32, 3), b(32, 8);
        wsplitT_kernel<<<g1, b>>>(fc1_w, w1h, w1l, K1, 1024);
        dim3 g2(1024 / 32, 1024 / 32, 3);
        wsplitT_kernel<<<g2, b>>>(fc2_w, w2h, w2l, 1024, 1024);
    }

    // cascade stages 0,1: refine rois
    for (int st = 0; st < 2; st++) {
        roi_align_kernel<<<alignGrid, 256>>>(P2, P3, P4, P5, H[0], H[1], H[2], H[3],
                                             rois_p, ph, pl);
        gemm_mma_kernel<<<dim3(16, mTiles, 1), 256, GEMM_SMEM>>>(
            ph, pl, w1h + (size_t)st * w1hd, w1l + (size_t)st * w1hd,
            fc1_b + st * 1024, nullptr, h1h, h1l, nroi, K1, 1, 0, 0, 0, 0);
        gemm_mma_kernel<<<dim3(16, mTiles, 1), 256, GEMM_SMEM>>>(
            h1h, h1l, w2h + (size_t)st * w2hd, w2l + (size_t)st * w2hd,
            fc2_b + st * 1024, h2_p, nullptr, nullptr, nroi, 1024, 1, 0, 0, 0, 0);
        gemm_small_kernel<<<dim3(nroi, 1), 256>>>(
            h2_p, reg_w + (size_t)st * 1024 * 4, reg_b + st * 4, deltas_p,
            4, 1024, 0, 0, 0, 0);
        delta2bbox_kernel<<<dbBlocks, 256>>>(rois_p, deltas_p, nroi);
    }

    // final pooled (stage-2 rois) + 3-head ensemble, batched
    roi_align_kernel<<<alignGrid, 256>>>(P2, P3, P4, P5, H[0], H[1], H[2], H[3],
                                         rois_p, ph, pl);
    // fc1 for all 3 heads in one GEMM: B rows = 3072 (heads contiguous in w1t)
    gemm_mma_kernel<<<dim3(48, mTiles, 1), 256, GEMM_SMEM>>>(
        ph, pl, w1h, w1l, fc1_b, nullptr, h1h, h1l, nroi, K1, 1, 0, 0, 0, 0);
    // fc2 for all 3 heads via blockIdx.z
    gemm_mma_kernel<<<dim3(16, mTiles, 3), 256, GEMM_SMEM>>>(
        h1h, h1l, w2h, w2l, fc2_b, h2_p, nullptr, nullptr, nroi, 1024, 1,
        mslab, (long)w2hd, 1024, mslab);
    // cls for all 3 heads via blockIdx.y
    gemm_small_kernel<<<dim3(nroi, 3), 256>>>(
        h2_p, cls_w, cls_b, logits_p, 81, 1024,
        mslab, (long)1024 * 81, 81, (long)nroi * 81);

    softmax_avg_kernel<<<nroi, 128>>>(logits_p, out, nroi);
}

// round 14
// speedup vs baseline: 1.3861x; 1.3861x over previous
#include <cuda_runtime.h>
#include <cuda_bf16.h>
#include <math.h>
#include <stdint.h>

// ---------------------------------------------------------------------------
// Scratch (__device__ globals; no allocations allowed)
// ---------------------------------------------------------------------------
#define MAXROI 2048
#define K1MAX  12544

__device__ __nv_bfloat16 g_w1t_hi[3u * 1024u * K1MAX];
__device__ __nv_bfloat16 g_w1t_lo[3u * 1024u * K1MAX];
__device__ __nv_bfloat16 g_w2t_hi[3u * 1024u * 1024u];
__device__ __nv_bfloat16 g_w2t_lo[3u * 1024u * 1024u];
__device__ __nv_bfloat16 g_pool_hi[MAXROI * K1MAX];
__device__ __nv_bfloat16 g_pool_lo[MAXROI * K1MAX];
__device__ __nv_bfloat16 g_h1_hi[3u * MAXROI * 1024u];
__device__ __nv_bfloat16 g_h1_lo[3u * MAXROI * 1024u];
__device__ float g_h2[3u * MAXROI * 1024u];
__device__ float g_logits[3 * MAXROI * 81];
__device__ float g_deltas[MAXROI * 4];
__device__ float g_rois[MAXROI * 4];
__device__ float g_clsT[3 * 81 * 1024];
__device__ float g_regT[3 * 4 * 1024];

// ---------------------------------------------------------------------------
// PTX helpers (baseline compute_103-legal instructions only)
// ---------------------------------------------------------------------------
__device__ __forceinline__ uint32_t smem_u32(const void* p) {
    uint32_t a;
    asm("{ .reg .u64 t; cvta.to.shared.u64 t, %1; cvt.u32.u64 %0, t; }" : "=r"(a) : "l"(p));
    return a;
}

#define CP_ASYNC16(dst, src) \
    asm volatile("cp.async.cg.shared.global [%0], [%1], 16;" :: "r"(dst), "l"(src) : "memory")
#define CP_ASYNC16_Z(dst, src, sz) \
    asm volatile("cp.async.cg.shared.global [%0], [%1], 16, %2;" :: "r"(dst), "l"(src), "r"(sz) : "memory")
#define CP_COMMIT()  asm volatile("cp.async.commit_group;" ::: "memory")
#define CP_WAIT1()   asm volatile("cp.async.wait_group 1;" ::: "memory")
#define CP_WAIT0()   asm volatile("cp.async.wait_group 0;" ::: "memory")

#define LDSM_X4(r, addr) \
    asm volatile("ldmatrix.sync.aligned.m8n8.x4.shared.b16 {%0,%1,%2,%3}, [%4];" \
        : "=r"((r)[0]), "=r"((r)[1]), "=r"((r)[2]), "=r"((r)[3]) : "r"(addr))

#define MMA16816(d, a, b) \
    asm volatile("mma.sync.aligned.m16n8k16.row.col.f32.bf16.bf16.f32 " \
        "{%0,%1,%2,%3}, {%4,%5,%6,%7}, {%8,%9}, {%0,%1,%2,%3};" \
        : "+f"((d)[0]), "+f"((d)[1]), "+f"((d)[2]), "+f"((d)[3]) \
        : "r"((a)[0]), "r"((a)[1]), "r"((a)[2]), "r"((a)[3]), "r"((b)[0]), "r"((b)[1]))

// ---------------------------------------------------------------------------
// Copy rois
// ---------------------------------------------------------------------------
__global__ void copy_rois_kernel(const float* __restrict__ src, float* __restrict__ dst, int n4) {
    int i = blockIdx.x * blockDim.x + threadIdx.x;
    if (i < n4) dst[i] = src[i];
}

// ---------------------------------------------------------------------------
// Weight transpose + bf16 split:  W[K,N] fp32  ->  WT_hi/lo [N,K] bf16
// ---------------------------------------------------------------------------
__global__ void wsplitT_kernel(const float* __restrict__ W,
                               __nv_bfloat16* __restrict__ Thi,
                               __nv_bfloat16* __restrict__ Tlo, int K, int N) {
    __shared__ float t[32][33];
    const int h = blockIdx.z;
    const float* Wp = W + (size_t)h * K * N;
    __nv_bfloat16* Hp = Thi + (size_t)h * N * K;
    __nv_bfloat16* Lp = Tlo + (size_t)h * N * K;
    const int k0 = blockIdx.x * 32, n0 = blockIdx.y * 32;
    const int tx = threadIdx.x, ty = threadIdx.y;
#pragma unroll
    for (int r = 0; r < 32; r += 8)
        t[ty + r][tx] = Wp[(size_t)(k0 + ty + r) * N + n0 + tx];
    __syncthreads();
#pragma unroll
    for (int r = 0; r < 32; r += 8) {
        float v = t[tx][ty + r];
        __nv_bfloat16 hi = __float2bfloat16(v);
        float lo = v - __bfloat162float(hi);
        size_t o = (size_t)(n0 + ty + r) * K + k0 + tx;
        Hp[o] = hi;
        Lp[o] = __float2bfloat16(lo);
    }
}

// ---------------------------------------------------------------------------
// fp32 transpose for small head weights:  W[K,N] -> WT[N,K]  (N may be ragged)
// grid (K/32, ceil(N/32), heads), block (32,8)
// ---------------------------------------------------------------------------
__global__ void wT_kernel(const float* __restrict__ W, float* __restrict__ WT,
                          int K, int N) {
    __shared__ float t[32][33];
    const int h = blockIdx.z;
    const float* Wp = W + (size_t)h * K * N;
    float* Tp = WT + (size_t)h * N * K;
    const int k0 = blockIdx.x * 32, n0 = blockIdx.y * 32;
    const int tx = threadIdx.x, ty = threadIdx.y;
#pragma unroll
    for (int r = 0; r < 32; r += 8) {
        if (n0 + tx < N)
            t[ty + r][tx] = Wp[(size_t)(k0 + ty + r) * N + n0 + tx];
    }
    __syncthreads();
#pragma unroll
    for (int r = 0; r < 32; r += 8) {
        if (n0 + ty + r < N)
            Tp[(size_t)(n0 + ty + r) * K + k0 + tx] = t[tx][ty + r];
    }
}

// ---------------------------------------------------------------------------
// Pyramid ROI align -> bf16 hi/lo.  grid (13, nroi), block 256.
// Block handles 4 pooled pixels; 64 threads per pixel, float4 channel loads.
// ---------------------------------------------------------------------------
__global__ void roi_align_kernel(
    const float* __restrict__ P2, const float* __restrict__ P3,
    const float* __restrict__ P4, const float* __restrict__ P5,
    int H2, int H3, int H4, int H5,
    const float* __restrict__ rois,
    __nv_bfloat16* __restrict__ phi, __nv_bfloat16* __restrict__ plo)
{
    __shared__ int   s_lvl;
    __shared__ int   s_o[4][4];
    __shared__ float s_w[4][4];

    const int n   = blockIdx.y;
    const int tid = threadIdx.x;

    if (tid < 4) {
        const int pp = blockIdx.x * 4 + tid;
        const float y1 = rois[n * 4 + 0];
        const float x1 = rois[n * 4 + 1];
        const float y2 = rois[n * 4 + 2];
        const float x2 = rois[n * 4 + 3];
        const float hh = y2 - y1, ww = x2 - x1;

        float hwv = fmaxf(hh * ww, 1e-6f);
        float lf  = floorf(4.0f + log2f(sqrtf(hwv) / 224.0f));
        lf = fminf(fmaxf(lf, 2.0f), 5.0f);
        const int li = (int)lf - 2;
        if (tid == 0) s_lvl = li;

        if (pp < 49) {
            const int py = pp / 7, px = pp % 7;
            int H;
            float stride;
            switch (li) {
                case 0:  H = H2; stride = 4.0f;  break;
                case 1:  H = H3; stride = 8.0f;  break;
                case 2:  H = H4; stride = 16.0f; break;
                default: H = H5; stride = 32.0f; break;
            }
            const float s0 = y1 / stride, s1 = x1 / stride;
            const float s2 = y2 / stride, s3 = x2 / stride;
            const float gy = ((float)py + 0.5f) / 7.0f;
            const float gx = ((float)px + 0.5f) / 7.0f;
            const float ys = __fadd_rn(s0, __fmul_rn(gy, __fsub_rn(s2, s0)));
            const float xs = __fadd_rn(s1, __fmul_rn(gx, __fsub_rn(s3, s1)));

            const float Hm1 = (float)(H - 1);
            const float y0f = fminf(fmaxf(floorf(ys), 0.0f), Hm1);
            const float x0f = fminf(fmaxf(floorf(xs), 0.0f), Hm1);
            const int y0 = (int)y0f, x0 = (int)x0f;
            const int y1i = min(y0 + 1, H - 1);
            const int x1i = min(x0 + 1, H - 1);
            const float wy = fminf(fmaxf(ys - y0f, 0.0f), 1.0f);
            const float wx = fminf(fmaxf(xs - x0f, 0.0f), 1.0f);
            const float omwy = 1.0f - wy, omwx = 1.0f - wx;

            s_o[tid][0] = (y0  * H + x0 ) * 256;
            s_o[tid][1] = (y0  * H + x1i) * 256;
            s_o[tid][2] = (y1i * H + x0 ) * 256;
            s_o[tid][3] = (y1i * H + x1i) * 256;
            s_w[tid][0] = omwy * omwx;
            s_w[tid][1] = omwy * wx;
            s_w[tid][2] = wy * omwx;
            s_w[tid][3] = wy * wx;
        }
    }
    __syncthreads();

    const int sub = tid >> 6;               // pixel within block
    const int cg  = tid & 63;               // channel group (4 ch)
    const int pp  = blockIdx.x * 4 + sub;
    if (pp >= 49) return;

    const float* feat;
    switch (s_lvl) {
        case 0:  feat = P2; break;
        case 1:  feat = P3; break;
        case 2:  feat = P4; break;
        default: feat = P5; break;
    }

    const float4 f00 = *((const float4*)(feat + s_o[sub][0]) + cg);
    const float4 f01 = *((const float4*)(feat + s_o[sub][1]) + cg);
    const float4 f10 = *((const float4*)(feat + s_o[sub][2]) + cg);
    const float4 f11 = *((const float4*)(feat + s_o[sub][3]) + cg);
    const float w0 = s_w[sub][0], w1 = s_w[sub][1], w2 = s_w[sub][2], w3 = s_w[sub][3];

    float4 r;
    r.x = f00.x * w0 + f01.x * w1 + f10.x * w2 + f11.x * w3;
    r.y = f00.y * w0 + f01.y * w1 + f10.y * w2 + f11.y * w3;
    r.z = f00.z * w0 + f01.z * w1 + f10.z * w2 + f11.z * w3;
    r.w = f00.w * w0 + f01.w * w1 + f10.w * w2 + f11.w * w3;

    const size_t idx = ((size_t)n * 49 + pp) * 256 + cg * 4;
    __nv_bfloat16 hx = __float2bfloat16(r.x);
    __nv_bfloat16 hy = __float2bfloat16(r.y);
    __nv_bfloat16 hz = __float2bfloat16(r.z);
    __nv_bfloat16 hw = __float2bfloat16(r.w);
    phi[idx + 0] = hx;  phi[idx + 1] = hy;  phi[idx + 2] = hz;  phi[idx + 3] = hw;
    plo[idx + 0] = __float2bfloat16(r.x - __bfloat162float(hx));
    plo[idx + 1] = __float2bfloat16(r.y - __bfloat162float(hy));
    plo[idx + 2] = __float2bfloat16(r.z - __bfloat162float(hz));
    plo[idx + 3] = __float2bfloat16(r.w - __bfloat162float(hw));
}

// ---------------------------------------------------------------------------
// mma.sync split-bf16 GEMM.  Logical output width is always 1024:
//   B has NB rows (1024, or 3072 for head-batched fc1); output column colg maps
//   to (head = colg>>10, col = colg&1023) at head*M*1024 + row*1024 + col.
// D += AhiBhi + AhiBlo + AloBhi (fp32 accum, ~2^-16).
// CTA tile 128x64, BK=32, 8 warps, 2-stage cp.async, 2 CTAs/SM.
// ---------------------------------------------------------------------------
__global__ __launch_bounds__(256, 2) void gemm_mma_kernel(
    const __nv_bfloat16* __restrict__ Ahi, const __nv_bfloat16* __restrict__ Alo,
    const __nv_bfloat16* __restrict__ Bhi, const __nv_bfloat16* __restrict__ Blo,
    const float* __restrict__ bias,
    float* __restrict__ Cf, __nv_bfloat16* __restrict__ Chi, __nv_bfloat16* __restrict__ Clo,
    int M, int K, int doRelu,
    long zA, long zB, long zBias, long zC)
{
    extern __shared__ char smem[];
    const uint32_t sb = smem_u32(smem);

    const int z = blockIdx.z;
    Ahi += (size_t)zA * z;  Alo += (size_t)zA * z;
    Bhi += (size_t)zB * z;  Blo += (size_t)zB * z;
    bias += (size_t)zBias * z;
    if (Cf)  Cf  += (size_t)zC * z;
    if (Chi) { Chi += (size_t)zC * z; Clo += (size_t)zC * z; }

    const int tid  = threadIdx.x;
    const int lane = tid & 31, warp = tid >> 5;
    const int warpM = warp & 3, warpN = warp >> 2;
    const int wm0 = warpM * 32, wn0 = warpN * 32;
    const int bm0 = blockIdx.y * 128, bn0 = blockIdx.x * 64;

    const uint32_t STAGE = 30720u;   // Ahi 10240 | Alo 10240 | Bhi 5120 | Blo 5120

    float acc[2][4][4];
#pragma unroll
    for (int mt = 0; mt < 2; mt++)
#pragma unroll
        for (int nt = 0; nt < 4; nt++)
#pragma unroll
            for (int i = 0; i < 4; i++) acc[mt][nt][i] = 0.0f;

    auto load_stage = [&](int s, int kc) {
        const int k0 = kc * 32;
        const uint32_t base = sb + (uint32_t)s * STAGE;
#pragma unroll
        for (int it = 0; it < 2; it++) {
            const int i   = tid + it * 256;
            const int row = i >> 2, cj = i & 3;
            const uint32_t d  = base + (uint32_t)row * 80u + (uint32_t)cj * 16u;
            const int gr = bm0 + row;
            const int sz = (gr < M) ? 16 : 0;
            const size_t go = (size_t)gr * K + k0 + cj * 8;
            CP_ASYNC16_Z(d,           Ahi + go, sz);
            CP_ASYNC16_Z(d + 10240u,  Alo + go, sz);
        }
        {
            const int row = tid >> 2, cj = tid & 3;
            const uint32_t d = base + 20480u + (uint32_t)row * 80u + (uint32_t)cj * 16u;
            const size_t go = (size_t)(bn0 + row) * K + k0 + cj * 8;
            CP_ASYNC16(d,          Bhi + go);
            CP_ASYNC16(d + 5120u,  Blo + go);
        }
        CP_COMMIT();
    };

    const uint32_t aRow = (uint32_t)(wm0 + (lane & 15));
    const uint32_t aCol = (uint32_t)((lane >> 4) * 16);
    const uint32_t bRow = (uint32_t)(wn0 + ((lane >> 4) & 1) * 8 + (lane & 7));
    const uint32_t bCol = (uint32_t)(((lane >> 3) & 1) * 16);

    const int nkc = K >> 5;
    load_stage(0, 0);

    for (int kc = 0; kc < nkc; kc++) {
        if (kc + 1 < nkc) {
            load_stage((kc + 1) & 1, kc + 1);
            CP_WAIT1();
        } else {
            CP_WAIT0();
        }
        __syncthreads();

        const uint32_t base = sb + (uint32_t)(kc & 1) * STAGE;
#pragma unroll
        for (int ks = 0; ks < 2; ks++) {
            uint32_t a_h[2][4], a_l[2][4];
#pragma unroll
            for (int mt = 0; mt < 2; mt++) {
                const uint32_t ad = base + (aRow + (uint32_t)mt * 16u) * 80u + aCol + (uint32_t)ks * 32u;
                LDSM_X4(a_h[mt], ad);
                LDSM_X4(a_l[mt], ad + 10240u);
            }
            uint32_t b_h[4][2], b_l[4][2];
#pragma unroll
            for (int p = 0; p < 2; p++) {
                const uint32_t bd = base + 20480u + (bRow + (uint32_t)p * 16u) * 80u + bCol + (uint32_t)ks * 32u;
                uint32_t r[4];
                LDSM_X4(r, bd);
                b_h[2*p][0] = r[0]; b_h[2*p][1] = r[1];
                b_h[2*p+1][0] = r[2]; b_h[2*p+1][1] = r[3];
                LDSM_X4(r, bd + 5120u);
                b_l[2*p][0] = r[0]; b_l[2*p][1] = r[1];
                b_l[2*p+1][0] = r[2]; b_l[2*p+1][1] = r[3];
            }
#pragma unroll
            for (int mt = 0; mt < 2; mt++)
#pragma unroll
                for (int nt = 0; nt < 4; nt++) {
                    MMA16816(acc[mt][nt], a_h[mt], b_h[nt]);
                    MMA16816(acc[mt][nt], a_h[mt], b_l[nt]);
                    MMA16816(acc[mt][nt], a_l[mt], b_h[nt]);
                }
        }
        __syncthreads();
    }

    // epilogue with head-aware column mapping (logical out width 1024)
    const int erow = lane >> 2;
    const int ecol = (lane & 3) * 2;
#pragma unroll
    for (int mt = 0; mt < 2; mt++)
#pragma unroll
        for (int nt = 0; nt < 4; nt++) {
            const int colg = bn0 + wn0 + nt * 8 + ecol;
            const int head = colg >> 10;
            const int col  = colg & 1023;
            const float b0v = bias[colg], b1v = bias[colg + 1];
            const size_t hbase = (size_t)head * M * 1024;
#pragma unroll
            for (int h = 0; h < 2; h++) {
                const int row = bm0 + wm0 + mt * 16 + erow + h * 8;
                if (row >= M) continue;
                float v0 = acc[mt][nt][h * 2 + 0] + b0v;
                float v1 = acc[mt][nt][h * 2 + 1] + b1v;
                if (doRelu) { v0 = fmaxf(v0, 0.0f); v1 = fmaxf(v1, 0.0f); }
                const size_t o = hbase + (size_t)row * 1024 + col;
                if (Cf) { Cf[o] = v0; Cf[o + 1] = v1; }
                if (Chi) {
                    __nv_bfloat16 h0 = __float2bfloat16(v0);
                    __nv_bfloat16 h1 = __float2bfloat16(v1);
                    Chi[o]     = h0;
                    Chi[o + 1] = h1;
                    Clo[o]     = __float2bfloat16(v0 - __bfloat162float(h0));
                    Clo[o + 1] = __float2bfloat16(v1 - __bfloat162float(h1));
                }
            }
        }
}

// ---------------------------------------------------------------------------
// Small-N GEMM with transposed weights WT[N,K] (coalesced rows).
// Block handles 4 A-rows; warp per output column; K = 1024.
// grid (ceil(M/4), nz), block 256.
// ---------------------------------------------------------------------------
__global__ __launch_bounds__(256) void gemm_smallT_kernel(
    const float* __restrict__ A, const float* __restrict__ WT,
    const float* __restrict__ bias, float* __restrict__ C, int M, int N,
    long zA, long zW, long zBias, long zC)
{
    __shared__ float a[4][1024];
    const int z = blockIdx.y;
    A += (size_t)zA * z;  WT += (size_t)zW * z;
    bias += (size_t)zBias * z;  C += (size_t)zC * z;

    const int row0 = blockIdx.x * 4;
    const int nr = min(4, M - row0);
    const int tid = threadIdx.x, lane = tid & 31, warp = tid >> 5;

    for (int i = tid; i < nr * 1024; i += 256)
        a[i >> 10][i & 1023] = A[(size_t)(row0 + (i >> 10)) * 1024 + (i & 1023)];
    __syncthreads();

    for (int col = warp; col < N; col += 8) {
        float s0 = 0.f, s1 = 0.f, s2 = 0.f, s3 = 0.f;
        const float* wrow = WT + (size_t)col * 1024;
        for (int k = lane; k < 1024; k += 32) {
            const float w = wrow[k];
            s0 += a[0][k] * w;
            s1 += a[1][k] * w;
            s2 += a[2][k] * w;
            s3 += a[3][k] * w;
        }
#pragma unroll
        for (int off = 16; off > 0; off >>= 1) {
            s0 += __shfl_xor_sync(0xFFFFFFFFu, s0, off);
            s1 += __shfl_xor_sync(0xFFFFFFFFu, s1, off);
            s2 += __shfl_xor_sync(0xFFFFFFFFu, s2, off);
            s3 += __shfl_xor_sync(0xFFFFFFFFu, s3, off);
        }
        if (lane == 0) {
            const float bv = bias[col];
            if (nr > 0) C[(size_t)(row0 + 0) * N + col] = s0 + bv;
            if (nr > 1) C[(size_t)(row0 + 1) * N + col] = s1 + bv;
            if (nr > 2) C[(size_t)(row0 + 2) * N + col] = s2 + bv;
            if (nr > 3) C[(size_t)(row0 + 3) * N + col] = s3 + bv;
        }
    }
}

// ---------------------------------------------------------------------------
// delta2bbox (in-place)
// ---------------------------------------------------------------------------
__global__ void delta2bbox_kernel(float* __restrict__ rois,
                                  const float* __restrict__ deltas, int nroi)
{
    int n = blockIdx.x * blockDim.x + threadIdx.x;
    if (n >= nroi) return;
    const float y1 = rois[n * 4 + 0];
    const float x1 = rois[n * 4 + 1];
    const float y2 = rois[n * 4 + 2];
    const float x2 = rois[n * 4 + 3];
    const float d0 = deltas[n * 4 + 0] * 0.1f;
    const float d1 = deltas[n * 4 + 1] * 0.1f;
    const float d2 = deltas[n * 4 + 2] * 0.2f;
    const float d3 = deltas[n * 4 + 3] * 0.2f;
    float h = y2 - y1;
    float w = x2 - x1;
    const float cy = y1 + 0.5f * h + d0 * h;
    const float cx = x1 + 0.5f * w + d1 * w;
    h = h * expf(d2);
    w = w * expf(d3);
    rois[n * 4 + 0] = fminf(fmaxf(cy - 0.5f * h, 0.0f), 1024.0f);
    rois[n * 4 + 1] = fminf(fmaxf(cx - 0.5f * w, 0.0f), 1024.0f);
    rois[n * 4 + 2] = fminf(fmaxf(cy + 0.5f * h, 0.0f), 1024.0f);
    rois[n * 4 + 3] = fminf(fmaxf(cx + 0.5f * w, 0.0f), 1024.0f);
}

// ---------------------------------------------------------------------------
// 3-head softmax average
// ---------------------------------------------------------------------------
__global__ __launch_bounds__(128) void softmax_avg_kernel(
    const float* __restrict__ logits, float* __restrict__ out, int nroi)
{
    __shared__ float red[128];
    const int n = blockIdx.x;
    const int c = threadIdx.x;
    float acc = 0.0f;

    for (int h = 0; h < 3; h++) {
        float v = (c < 81) ? logits[(size_t)h * nroi * 81 + (size_t)n * 81 + c] : -3.0e38f;
        red[c] = v;
        __syncthreads();
#pragma unroll
        for (int s = 64; s > 0; s >>= 1) {
            if (c < s) red[c] = fmaxf(red[c], red[c + s]);
            __syncthreads();
        }
        const float m = red[0];
        __syncthreads();
        const float e = (c < 81) ? expf(v - m) : 0.0f;
        red[c] = e;
        __syncthreads();
#pragma unroll
        for (int s = 64; s > 0; s >>= 1) {
            if (c < s) red[c] += red[c + s];
            __syncthreads();
        }
        const float ssum = red[0];
        __syncthreads();
        acc += e / ssum;
    }
    if (c < 81) out[(size_t)n * 81 + c] = acc / 3.0f;
}

// ---------------------------------------------------------------------------
// Launcher
// ---------------------------------------------------------------------------
extern "C" void kernel_launch(void* const* d_in, const int* in_sizes, int n_in,
                              void* d_out, int out_size)
{
    const float* P2    = (const float*)d_in[0];
    const float* P3    = (const float*)d_in[1];
    const float* P4    = (const float*)d_in[2];
    const float* P5    = (const float*)d_in[3];
    const float* rois  = (const float*)d_in[4];
    const float* fc1_w = (const float*)d_in[5];
    const float* fc1_b = (const float*)d_in[6];
    const float* fc2_w = (const float*)d_in[7];
    const float* fc2_b = (const float*)d_in[8];
    const float* cls_w = (const float*)d_in[9];
    const float* cls_b = (const float*)d_in[10];
    const float* reg_w = (const float*)d_in[11];
    const float* reg_b = (const float*)d_in[12];
    float* out = (float*)d_out;

    const int nroi = in_sizes[4] / 4;
    if (nroi <= 0 || nroi > MAXROI) return;

    int H[4];
    for (int i = 0; i < 4; i++) {
        double e = (double)in_sizes[i] / 256.0;
        H[i] = (int)(sqrt(e) + 0.5);
    }
    const int K1 = in_sizes[5] / (3 * 1024);   // 12544
    if (K1 > K1MAX || (K1 & 31)) return;

    __nv_bfloat16 *w1h, *w1l, *w2h, *w2l, *ph, *pl, *h1h, *h1l;
    float *h2_p, *logits_p, *deltas_p, *rois_p, *clsT_p, *regT_p;
    cudaGetSymbolAddress((void**)&w1h, g_w1t_hi);
    cudaGetSymbolAddress((void**)&w1l, g_w1t_lo);
    cudaGetSymbolAddress((void**)&w2h, g_w2t_hi);
    cudaGetSymbolAddress((void**)&w2l, g_w2t_lo);
    cudaGetSymbolAddress((void**)&ph,  g_pool_hi);
    cudaGetSymbolAddress((void**)&pl,  g_pool_lo);
    cudaGetSymbolAddress((void**)&h1h, g_h1_hi);
    cudaGetSymbolAddress((void**)&h1l, g_h1_lo);
    cudaGetSymbolAddress((void**)&h2_p,     g_h2);
    cudaGetSymbolAddress((void**)&logits_p, g_logits);
    cudaGetSymbolAddress((void**)&deltas_p, g_deltas);
    cudaGetSymbolAddress((void**)&rois_p,   g_rois);
    cudaGetSymbolAddress((void**)&clsT_p,   g_clsT);
    cudaGetSymbolAddress((void**)&regT_p,   g_regT);

    const int GEMM_SMEM = 2 * 30720;   // 61440 B -> 2 CTAs/SM
    cudaFuncSetAttribute(gemm_mma_kernel, cudaFuncAttributeMaxDynamicSharedMemorySize, GEMM_SMEM);

    const dim3 alignGrid(13, nroi);
    const int mTiles = (nroi + 127) / 128;
    const int cpBlocks = (nroi * 4 + 255) / 256;
    const int dbBlocks = (nroi + 255) / 256;
    const size_t w1hd = (size_t)1024 * K1;
    const size_t w2hd = (size_t)1024 * 1024;
    const long mslab = (long)nroi * 1024;
    const int smallGrid = (nroi + 3) / 4;

    copy_rois_kernel<<<cpBlocks, 256>>>(rois, rois_p, nroi * 4);

    // weight transforms
    {
        dim3 b(32, 8);
        wsplitT_kernel<<<dim3(K1 / 32, 1024 / 32, 3), b>>>(fc1_w, w1h, w1l, K1, 1024);
        wsplitT_kernel<<<dim3(1024 / 32, 1024 / 32, 3), b>>>(fc2_w, w2h, w2l, 1024, 1024);
        wT_kernel<<<dim3(1024 / 32, (81 + 31) / 32, 3), b>>>(cls_w, clsT_p, 1024, 81);
        wT_kernel<<<dim3(1024 / 32, 1, 3), b>>>(reg_w, regT_p, 1024, 4);
    }

    // cascade stages 0,1: refine rois
    for (int st = 0; st < 2; st++) {
        roi_align_kernel<<<alignGrid, 256>>>(P2, P3, P4, P5, H[0], H[1], H[2], H[3],
                                             rois_p, ph, pl);
        gemm_mma_kernel<<<dim3(16, mTiles, 1), 256, GEMM_SMEM>>>(
            ph, pl, w1h + (size_t)st * w1hd, w1l + (size_t)st * w1hd,
            fc1_b + st * 1024, nullptr, h1h, h1l, nroi, K1, 1, 0, 0, 0, 0);
        gemm_mma_kernel<<<dim3(16, mTiles, 1), 256, GEMM_SMEM>>>(
            h1h, h1l, w2h + (size_t)st * w2hd, w2l + (size_t)st * w2hd,
            fc2_b + st * 1024, h2_p, nullptr, nullptr, nroi, 1024, 1, 0, 0, 0, 0);
        gemm_smallT_kernel<<<dim3(smallGrid, 1), 256>>>(
            h2_p, regT_p + (size_t)st * 4 * 1024, reg_b + st * 4, deltas_p,
            nroi, 4, 0, 0, 0, 0);
        delta2bbox_kernel<<<dbBlocks, 256>>>(rois_p, deltas_p, nroi);
    }

    // final pooled (stage-2 rois) + 3-head ensemble, batched
    roi_align_kernel<<<alignGrid, 256>>>(P2, P3, P4, P5, H[0], H[1], H[2], H[3],
                                         rois_p, ph, pl);
    gemm_mma_kernel<<<dim3(48, mTiles, 1), 256, GEMM_SMEM>>>(
        ph, pl, w1h, w1l, fc1_b, nullptr, h1h, h1l, nroi, K1, 1, 0, 0, 0, 0);
    gemm_mma_kernel<<<dim3(16, mTiles, 3), 256, GEMM_SMEM>>>(
        h1h, h1l, w2h, w2l, fc2_b, h2_p, nullptr, nullptr, nroi, 1024, 1,
        mslab, (long)w2hd, 1024, mslab);
    gemm_smallT_kernel<<<dim3(smallGrid, 3), 256>>>(
        h2_p, clsT_p, cls_b, logits_p, nroi, 81,
        mslab, (long)81 * 1024, 81, (long)nroi * 81);

    softmax_avg_kernel<<<nroi, 128>>>(logits_p, out, nroi);
}

// round 15
// speedup vs baseline: 1.3869x; 1.0006x over previous
#include <cuda_runtime.h>
#include <cuda_bf16.h>
#include <math.h>
#include <stdint.h>

// ---------------------------------------------------------------------------
// Scratch (__device__ globals; no allocations allowed)
// ---------------------------------------------------------------------------
#define MAXROI 2048
#define K1MAX  12544

__device__ __nv_bfloat16 g_w1t_hi[3u * 1024u * K1MAX];
__device__ __nv_bfloat16 g_w1t_lo[3u * 1024u * K1MAX];
__device__ __nv_bfloat16 g_w2t_hi[3u * 1024u * 1024u];
__device__ __nv_bfloat16 g_w2t_lo[3u * 1024u * 1024u];
__device__ __nv_bfloat16 g_pool_hi[MAXROI * K1MAX];
__device__ __nv_bfloat16 g_pool_lo[MAXROI * K1MAX];
__device__ __nv_bfloat16 g_h1_hi[3u * MAXROI * 1024u];
__device__ __nv_bfloat16 g_h1_lo[3u * MAXROI * 1024u];
__device__ float g_h2[3u * MAXROI * 1024u];
__device__ float g_logits[3 * MAXROI * 81];
__device__ float g_deltas[MAXROI * 4];
__device__ float g_rois[MAXROI * 4];
__device__ float g_clsT[3 * 81 * 1024];
__device__ float g_regT[3 * 4 * 1024];

// ---------------------------------------------------------------------------
// PTX helpers (baseline compute_103-legal instructions only)
// ---------------------------------------------------------------------------
__device__ __forceinline__ uint32_t smem_u32(const void* p) {
    uint32_t a;
    asm("{ .reg .u64 t; cvta.to.shared.u64 t, %1; cvt.u32.u64 %0, t; }" : "=r"(a) : "l"(p));
    return a;
}

#define CP_ASYNC16(dst, src) \
    asm volatile("cp.async.cg.shared.global [%0], [%1], 16;" :: "r"(dst), "l"(src) : "memory")
#define CP_ASYNC16_Z(dst, src, sz) \
    asm volatile("cp.async.cg.shared.global [%0], [%1], 16, %2;" :: "r"(dst), "l"(src), "r"(sz) : "memory")
#define CP_COMMIT()  asm volatile("cp.async.commit_group;" ::: "memory")
#define CP_WAIT1()   asm volatile("cp.async.wait_group 1;" ::: "memory")
#define CP_WAIT0()   asm volatile("cp.async.wait_group 0;" ::: "memory")

#define LDSM_X4(r, addr) \
    asm volatile("ldmatrix.sync.aligned.m8n8.x4.shared.b16 {%0,%1,%2,%3}, [%4];" \
        : "=r"((r)[0]), "=r"((r)[1]), "=r"((r)[2]), "=r"((r)[3]) : "r"(addr))

#define MMA16816(d, a, b) \
    asm volatile("mma.sync.aligned.m16n8k16.row.col.f32.bf16.bf16.f32 " \
        "{%0,%1,%2,%3}, {%4,%5,%6,%7}, {%8,%9}, {%0,%1,%2,%3};" \
        : "+f"((d)[0]), "+f"((d)[1]), "+f"((d)[2]), "+f"((d)[3]) \
        : "r"((a)[0]), "r"((a)[1]), "r"((a)[2]), "r"((a)[3]), "r"((b)[0]), "r"((b)[1]))

// ---------------------------------------------------------------------------
// Copy rois
// ---------------------------------------------------------------------------
__global__ void copy_rois_kernel(const float* __restrict__ src, float* __restrict__ dst, int n4) {
    int i = blockIdx.x * blockDim.x + threadIdx.x;
    if (i < n4) dst[i] = src[i];
}

// ---------------------------------------------------------------------------
// Weight transpose + bf16 split:  W[K,N] fp32  ->  WT_hi/lo [N,K] bf16
// ---------------------------------------------------------------------------
__global__ void wsplitT_kernel(const float* __restrict__ W,
                               __nv_bfloat16* __restrict__ Thi,
                               __nv_bfloat16* __restrict__ Tlo, int K, int N) {
    __shared__ float t[32][33];
    const int h = blockIdx.z;
    const float* Wp = W + (size_t)h * K * N;
    __nv_bfloat16* Hp = Thi + (size_t)h * N * K;
    __nv_bfloat16* Lp = Tlo + (size_t)h * N * K;
    const int k0 = blockIdx.x * 32, n0 = blockIdx.y * 32;
    const int tx = threadIdx.x, ty = threadIdx.y;
#pragma unroll
    for (int r = 0; r < 32; r += 8)
        t[ty + r][tx] = Wp[(size_t)(k0 + ty + r) * N + n0 + tx];
    __syncthreads();
#pragma unroll
    for (int r = 0; r < 32; r += 8) {
        float v = t[tx][ty + r];
        __nv_bfloat16 hi = __float2bfloat16(v);
        float lo = v - __bfloat162float(hi);
        size_t o = (size_t)(n0 + ty + r) * K + k0 + tx;
        Hp[o] = hi;
        Lp[o] = __float2bfloat16(lo);
    }
}

// ---------------------------------------------------------------------------
// fp32 transpose for small head weights:  W[K,N] -> WT[N,K]  (N may be ragged)
// grid (K/32, ceil(N/32), heads), block (32,8)
// ---------------------------------------------------------------------------
__global__ void wT_kernel(const float* __restrict__ W, float* __restrict__ WT,
                          int K, int N) {
    __shared__ float t[32][33];
    const int h = blockIdx.z;
    const float* Wp = W + (size_t)h * K * N;
    float* Tp = WT + (size_t)h * N * K;
    const int k0 = blockIdx.x * 32, n0 = blockIdx.y * 32;
    const int tx = threadIdx.x, ty = threadIdx.y;
#pragma unroll
    for (int r = 0; r < 32; r += 8) {
        if (n0 + tx < N)
            t[ty + r][tx] = Wp[(size_t)(k0 + ty + r) * N + n0 + tx];
    }
    __syncthreads();
#pragma unroll
    for (int r = 0; r < 32; r += 8) {
        if (n0 + ty + r < N)
            Tp[(size_t)(n0 + ty + r) * K + k0 + tx] = t[tx][ty + r];
    }
}

// ---------------------------------------------------------------------------
// Pyramid ROI align -> bf16 hi/lo.  grid (13, nroi), block 256.
// Block handles 4 pooled pixels; 64 threads per pixel, float4 channel loads.
// ---------------------------------------------------------------------------
__global__ void roi_align_kernel(
    const float* __restrict__ P2, const float* __restrict__ P3,
    const float* __restrict__ P4, const float* __restrict__ P5,
    int H2, int H3, int H4, int H5,
    const float* __restrict__ rois,
    __nv_bfloat16* __restrict__ phi, __nv_bfloat16* __restrict__ plo)
{
    __shared__ int   s_lvl;
    __shared__ int   s_o[4][4];
    __shared__ float s_w[4][4];

    const int n   = blockIdx.y;
    const int tid = threadIdx.x;

    if (tid < 4) {
        const int pp = blockIdx.x * 4 + tid;
        const float y1 = rois[n * 4 + 0];
        const float x1 = rois[n * 4 + 1];
        const float y2 = rois[n * 4 + 2];
        const float x2 = rois[n * 4 + 3];
        const float hh = y2 - y1, ww = x2 - x1;

        float hwv = fmaxf(hh * ww, 1e-6f);
        float lf  = floorf(4.0f + log2f(sqrtf(hwv) / 224.0f));
        lf = fminf(fmaxf(lf, 2.0f), 5.0f);
        const int li = (int)lf - 2;
        if (tid == 0) s_lvl = li;

        if (pp < 49) {
            const int py = pp / 7, px = pp % 7;
            int H;
            float stride;
            switch (li) {
                case 0:  H = H2; stride = 4.0f;  break;
                case 1:  H = H3; stride = 8.0f;  break;
                case 2:  H = H4; stride = 16.0f; break;
                default: H = H5; stride = 32.0f; break;
            }
            const float s0 = y1 / stride, s1 = x1 / stride;
            const float s2 = y2 / stride, s3 = x2 / stride;
            const float gy = ((float)py + 0.5f) / 7.0f;
            const float gx = ((float)px + 0.5f) / 7.0f;
            const float ys = __fadd_rn(s0, __fmul_rn(gy, __fsub_rn(s2, s0)));
            const float xs = __fadd_rn(s1, __fmul_rn(gx, __fsub_rn(s3, s1)));

            const float Hm1 = (float)(H - 1);
            const float y0f = fminf(fmaxf(floorf(ys), 0.0f), Hm1);
            const float x0f = fminf(fmaxf(floorf(xs), 0.0f), Hm1);
            const int y0 = (int)y0f, x0 = (int)x0f;
            const int y1i = min(y0 + 1, H - 1);
            const int x1i = min(x0 + 1, H - 1);
            const float wy = fminf(fmaxf(ys - y0f, 0.0f), 1.0f);
            const float wx = fminf(fmaxf(xs - x0f, 0.0f), 1.0f);
            const float omwy = 1.0f - wy, omwx = 1.0f - wx;

            s_o[tid][0] = (y0  * H + x0 ) * 256;
            s_o[tid][1] = (y0  * H + x1i) * 256;
            s_o[tid][2] = (y1i * H + x0 ) * 256;
            s_o[tid][3] = (y1i * H + x1i) * 256;
            s_w[tid][0] = omwy * omwx;
            s_w[tid][1] = omwy * wx;
            s_w[tid][2] = wy * omwx;
            s_w[tid][3] = wy * wx;
        }
    }
    __syncthreads();

    const int sub = tid >> 6;               // pixel within block
    const int cg  = tid & 63;               // channel group (4 ch)
    const int pp  = blockIdx.x * 4 + sub;
    if (pp >= 49) return;

    const float* feat;
    switch (s_lvl) {
        case 0:  feat = P2; break;
        case 1:  feat = P3; break;
        case 2:  feat = P4; break;
        default: feat = P5; break;
    }

    const float4 f00 = *((const float4*)(feat + s_o[sub][0]) + cg);
    const float4 f01 = *((const float4*)(feat + s_o[sub][1]) + cg);
    const float4 f10 = *((const float4*)(feat + s_o[sub][2]) + cg);
    const float4 f11 = *((const float4*)(feat + s_o[sub][3]) + cg);
    const float w0 = s_w[sub][0], w1 = s_w[sub][1], w2 = s_w[sub][2], w3 = s_w[sub][3];

    float4 r;
    r.x = f00.x * w0 + f01.x * w1 + f10.x * w2 + f11.x * w3;
    r.y = f00.y * w0 + f01.y * w1 + f10.y * w2 + f11.y * w3;
    r.z = f00.z * w0 + f01.z * w1 + f10.z * w2 + f11.z * w3;
    r.w = f00.w * w0 + f01.w * w1 + f10.w * w2 + f11.w * w3;

    const size_t idx = ((size_t)n * 49 + pp) * 256 + cg * 4;
    __nv_bfloat16 hx = __float2bfloat16(r.x);
    __nv_bfloat16 hy = __float2bfloat16(r.y);
    __nv_bfloat16 hz = __float2bfloat16(r.z);
    __nv_bfloat16 hw = __float2bfloat16(r.w);
    phi[idx + 0] = hx;  phi[idx + 1] = hy;  phi[idx + 2] = hz;  phi[idx + 3] = hw;
    plo[idx + 0] = __float2bfloat16(r.x - __bfloat162float(hx));
    plo[idx + 1] = __float2bfloat16(r.y - __bfloat162float(hy));
    plo[idx + 2] = __float2bfloat16(r.z - __bfloat162float(hz));
    plo[idx + 3] = __float2bfloat16(r.w - __bfloat162float(hw));
}

// ---------------------------------------------------------------------------
// mma.sync split-bf16 GEMM.  Logical output width is always 1024:
//   B has NB rows (1024, or 3072 for head-batched fc1); output column colg maps
//   to (head = colg>>10, col = colg&1023) at head*M*1024 + row*1024 + col.
// D += AhiBhi + AhiBlo + AloBhi (fp32 accum, ~2^-16).
// CTA tile 128x64, BK=32, 8 warps, 2-stage cp.async, 2 CTAs/SM.
// ---------------------------------------------------------------------------
__global__ __launch_bounds__(256, 2) void gemm_mma_kernel(
    const __nv_bfloat16* __restrict__ Ahi, const __nv_bfloat16* __restrict__ Alo,
    const __nv_bfloat16* __restrict__ Bhi, const __nv_bfloat16* __restrict__ Blo,
    const float* __restrict__ bias,
    float* __restrict__ Cf, __nv_bfloat16* __restrict__ Chi, __nv_bfloat16* __restrict__ Clo,
    int M, int K, int doRelu,
    long zA, long zB, long zBias, long zC)
{
    extern __shared__ char smem[];
    const uint32_t sb = smem_u32(smem);

    const int z = blockIdx.z;
    Ahi += (size_t)zA * z;  Alo += (size_t)zA * z;
    Bhi += (size_t)zB * z;  Blo += (size_t)zB * z;
    bias += (size_t)zBias * z;
    if (Cf)  Cf  += (size_t)zC * z;
    if (Chi) { Chi += (size_t)zC * z; Clo += (size_t)zC * z; }

    const int tid  = threadIdx.x;
    const int lane = tid & 31, warp = tid >> 5;
    const int warpM = warp & 3, warpN = warp >> 2;
    const int wm0 = warpM * 32, wn0 = warpN * 32;
    const int bm0 = blockIdx.y * 128, bn0 = blockIdx.x * 64;

    const uint32_t STAGE = 30720u;   // Ahi 10240 | Alo 10240 | Bhi 5120 | Blo 5120

    float acc[2][4][4];
#pragma unroll
    for (int mt = 0; mt < 2; mt++)
#pragma unroll
        for (int nt = 0; nt < 4; nt++)
#pragma unroll
            for (int i = 0; i < 4; i++) acc[mt][nt][i] = 0.0f;

    auto load_stage = [&](int s, int kc) {
        const int k0 = kc * 32;
        const uint32_t base = sb + (uint32_t)s * STAGE;
#pragma unroll
        for (int it = 0; it < 2; it++) {
            const int i   = tid + it * 256;
            const int row = i >> 2, cj = i & 3;
            const uint32_t d  = base + (uint32_t)row * 80u + (uint32_t)cj * 16u;
            const int gr = bm0 + row;
            const int sz = (gr < M) ? 16 : 0;
            const size_t go = (size_t)gr * K + k0 + cj * 8;
            CP_ASYNC16_Z(d,           Ahi + go, sz);
            CP_ASYNC16_Z(d + 10240u,  Alo + go, sz);
        }
        {
            const int row = tid >> 2, cj = tid & 3;
            const uint32_t d = base + 20480u + (uint32_t)row * 80u + (uint32_t)cj * 16u;
            const size_t go = (size_t)(bn0 + row) * K + k0 + cj * 8;
            CP_ASYNC16(d,          Bhi + go);
            CP_ASYNC16(d + 5120u,  Blo + go);
        }
        CP_COMMIT();
    };

    const uint32_t aRow = (uint32_t)(wm0 + (lane & 15));
    const uint32_t aCol = (uint32_t)((lane >> 4) * 16);
    const uint32_t bRow = (uint32_t)(wn0 + ((lane >> 4) & 1) * 8 + (lane & 7));
    const uint32_t bCol = (uint32_t)(((lane >> 3) & 1) * 16);

    const int nkc = K >> 5;
    load_stage(0, 0);

    for (int kc = 0; kc < nkc; kc++) {
        if (kc + 1 < nkc) {
            load_stage((kc + 1) & 1, kc + 1);
            CP_WAIT1();
        } else {
            CP_WAIT0();
        }
        __syncthreads();

        const uint32_t base = sb + (uint32_t)(kc & 1) * STAGE;
#pragma unroll
        for (int ks = 0; ks < 2; ks++) {
            uint32_t a_h[2][4], a_l[2][4];
#pragma unroll
            for (int mt = 0; mt < 2; mt++) {
                const uint32_t ad = base + (aRow + (uint32_t)mt * 16u) * 80u + aCol + (uint32_t)ks * 32u;
                LDSM_X4(a_h[mt], ad);
                LDSM_X4(a_l[mt], ad + 10240u);
            }
            uint32_t b_h[4][2], b_l[4][2];
#pragma unroll
            for (int p = 0; p < 2; p++) {
                const uint32_t bd = base + 20480u + (bRow + (uint32_t)p * 16u) * 80u + bCol + (uint32_t)ks * 32u;
                uint32_t r[4];
                LDSM_X4(r, bd);
                b_h[2*p][0] = r[0]; b_h[2*p][1] = r[1];
                b_h[2*p+1][0] = r[2]; b_h[2*p+1][1] = r[3];
                LDSM_X4(r, bd + 5120u);
                b_l[2*p][0] = r[0]; b_l[2*p][1] = r[1];
                b_l[2*p+1][0] = r[2]; b_l[2*p+1][1] = r[3];
            }
#pragma unroll
            for (int mt = 0; mt < 2; mt++)
#pragma unroll
                for (int nt = 0; nt < 4; nt++) {
                    MMA16816(acc[mt][nt], a_h[mt], b_h[nt]);
                    MMA16816(acc[mt][nt], a_h[mt], b_l[nt]);
                    MMA16816(acc[mt][nt], a_l[mt], b_h[nt]);
                }
        }
        __syncthreads();
    }

    // epilogue with head-aware column mapping (logical out width 1024)
    const int erow = lane >> 2;
    const int ecol = (lane & 3) * 2;
#pragma unroll
    for (int mt = 0; mt < 2; mt++)
#pragma unroll
        for (int nt = 0; nt < 4; nt++) {
            const int colg = bn0 + wn0 + nt * 8 + ecol;
            const int head = colg >> 10;
            const int col  = colg & 1023;
            const float b0v = bias[colg], b1v = bias[colg + 1];
            const size_t hbase = (size_t)head * M * 1024;
#pragma unroll
            for (int h = 0; h < 2; h++) {
                const int row = bm0 + wm0 + mt * 16 + erow + h * 8;
                if (row >= M) continue;
                float v0 = acc[mt][nt][h * 2 + 0] + b0v;
                float v1 = acc[mt][nt][h * 2 + 1] + b1v;
                if (doRelu) { v0 = fmaxf(v0, 0.0f); v1 = fmaxf(v1, 0.0f); }
                const size_t o = hbase + (size_t)row * 1024 + col;
                if (Cf) { Cf[o] = v0; Cf[o + 1] = v1; }
                if (Chi) {
                    __nv_bfloat16 h0 = __float2bfloat16(v0);
                    __nv_bfloat16 h1 = __float2bfloat16(v1);
                    Chi[o]     = h0;
                    Chi[o + 1] = h1;
                    Clo[o]     = __float2bfloat16(v0 - __bfloat162float(h0));
                    Clo[o + 1] = __float2bfloat16(v1 - __bfloat162float(h1));
                }
            }
        }
}

// ---------------------------------------------------------------------------
// Small-N GEMM with transposed weights WT[N,K] (coalesced rows).
// Block handles 4 A-rows; warp per output column; K = 1024.
// grid (ceil(M/4), nz), block 256.
// ---------------------------------------------------------------------------
__global__ __launch_bounds__(256) void gemm_smallT_kernel(
    const float* __restrict__ A, const float* __restrict__ WT,
    const float* __restrict__ bias, float* __restrict__ C, int M, int N,
    long zA, long zW, long zBias, long zC)
{
    __shared__ float a[4][1024];
    const int z = blockIdx.y;
    A += (size_t)zA * z;  WT += (size_t)zW * z;
    bias += (size_t)zBias * z;  C += (size_t)zC * z;

    const int row0 = blockIdx.x * 4;
    const int nr = min(4, M - row0);
    const int tid = threadIdx.x, lane = tid & 31, warp = tid >> 5;

    for (int i = tid; i < nr * 1024; i += 256)
        a[i >> 10][i & 1023] = A[(size_t)(row0 + (i >> 10)) * 1024 + (i & 1023)];
    __syncthreads();

    for (int col = warp; col < N; col += 8) {
        float s0 = 0.f, s1 = 0.f, s2 = 0.f, s3 = 0.f;
        const float* wrow = WT + (size_t)col * 1024;
        for (int k = lane; k < 1024; k += 32) {
            const float w = wrow[k];
            s0 += a[0][k] * w;
            s1 += a[1][k] * w;
            s2 += a[2][k] * w;
            s3 += a[3][k] * w;
        }
#pragma unroll
        for (int off = 16; off > 0; off >>= 1) {
            s0 += __shfl_xor_sync(0xFFFFFFFFu, s0, off);
            s1 += __shfl_xor_sync(0xFFFFFFFFu, s1, off);
            s2 += __shfl_xor_sync(0xFFFFFFFFu, s2, off);
            s3 += __shfl_xor_sync(0xFFFFFFFFu, s3, off);
        }
        if (lane == 0) {
            const float bv = bias[col];
            if (nr > 0) C[(size_t)(row0 + 0) * N + col] = s0 + bv;
            if (nr > 1) C[(size_t)(row0 + 1) * N + col] = s1 + bv;
            if (nr > 2) C[(size_t)(row0 + 2) * N + col] = s2 + bv;
            if (nr > 3) C[(size_t)(row0 + 3) * N + col] = s3 + bv;
        }
    }
}

// ---------------------------------------------------------------------------
// delta2bbox (in-place)
// ---------------------------------------------------------------------------
__global__ void delta2bbox_kernel(float* __restrict__ rois,
                                  const float* __restrict__ deltas, int nroi)
{
    int n = blockIdx.x * blockDim.x + threadIdx.x;
    if (n >= nroi) return;
    const float y1 = rois[n * 4 + 0];
    const float x1 = rois[n * 4 + 1];
    const float y2 = rois[n * 4 + 2];
    const float x2 = rois[n * 4 + 3];
    const float d0 = deltas[n * 4 + 0] * 0.1f;
    const float d1 = deltas[n * 4 + 1] * 0.1f;
    const float d2 = deltas[n * 4 + 2] * 0.2f;
    const float d3 = deltas[n * 4 + 3] * 0.2f;
    float h = y2 - y1;
    float w = x2 - x1;
    const float cy = y1 + 0.5f * h + d0 * h;
    const float cx = x1 + 0.5f * w + d1 * w;
    h = h * expf(d2);
    w = w * expf(d3);
    rois[n * 4 + 0] = fminf(fmaxf(cy - 0.5f * h, 0.0f), 1024.0f);
    rois[n * 4 + 1] = fminf(fmaxf(cx - 0.5f * w, 0.0f), 1024.0f);
    rois[n * 4 + 2] = fminf(fmaxf(cy + 0.5f * h, 0.0f), 1024.0f);
    rois[n * 4 + 3] = fminf(fmaxf(cx + 0.5f * w, 0.0f), 1024.0f);
}

// ---------------------------------------------------------------------------
// 3-head softmax average
// ---------------------------------------------------------------------------
__global__ __launch_bounds__(128) void softmax_avg_kernel(
    const float* __restrict__ logits, float* __restrict__ out, int nroi)
{
    __shared__ float red[128];
    const int n = blockIdx.x;
    const int c = threadIdx.x;
    float acc = 0.0f;

    for (int h = 0; h < 3; h++) {
        float v = (c < 81) ? logits[(size_t)h * nroi * 81 + (size_t)n * 81 + c] : -3.0e38f;
        red[c] = v;
        __syncthreads();
#pragma unroll
        for (int s = 64; s > 0; s >>= 1) {
            if (c < s) red[c] = fmaxf(red[c], red[c + s]);
            __syncthreads();
        }
        const float m = red[0];
        __syncthreads();
        const float e = (c < 81) ? expf(v - m) : 0.0f;
        red[c] = e;
        __syncthreads();
#pragma unroll
        for (int s = 64; s > 0; s >>= 1) {
            if (c < s) red[c] += red[c + s];
            __syncthreads();
        }
        const float ssum = red[0];
        __syncthreads();
        acc += e / ssum;
    }
    if (c < 81) out[(size_t)n * 81 + c] = acc / 3.0f;
}

// ---------------------------------------------------------------------------
// Launcher
// ---------------------------------------------------------------------------
extern "C" void kernel_launch(void* const* d_in, const int* in_sizes, int n_in,
                              void* d_out, int out_size)
{
    const float* P2    = (const float*)d_in[0];
    const float* P3    = (const float*)d_in[1];
    const float* P4    = (const float*)d_in[2];
    const float* P5    = (const float*)d_in[3];
    const float* rois  = (const float*)d_in[4];
    const float* fc1_w = (const float*)d_in[5];
    const float* fc1_b = (const float*)d_in[6];
    const float* fc2_w = (const float*)d_in[7];
    const float* fc2_b = (const float*)d_in[8];
    const float* cls_w = (const float*)d_in[9];
    const float* cls_b = (const float*)d_in[10];
    const float* reg_w = (const float*)d_in[11];
    const float* reg_b = (const float*)d_in[12];
    float* out = (float*)d_out;

    const int nroi = in_sizes[4] / 4;
    if (nroi <= 0 || nroi > MAXROI) return;

    int H[4];
    for (int i = 0; i < 4; i++) {
        double e = (double)in_sizes[i] / 256.0;
        H[i] = (int)(sqrt(e) + 0.5);
    }
    const int K1 = in_sizes[5] / (3 * 1024);   // 12544
    if (K1 > K1MAX || (K1 & 31)) return;

    __nv_bfloat16 *w1h, *w1l, *w2h, *w2l, *ph, *pl, *h1h, *h1l;
    float *h2_p, *logits_p, *deltas_p, *rois_p, *clsT_p, *regT_p;
    cudaGetSymbolAddress((void**)&w1h, g_w1t_hi);
    cudaGetSymbolAddress((void**)&w1l, g_w1t_lo);
    cudaGetSymbolAddress((void**)&w2h, g_w2t_hi);
    cudaGetSymbolAddress((void**)&w2l, g_w2t_lo);
    cudaGetSymbolAddress((void**)&ph,  g_pool_hi);
    cudaGetSymbolAddress((void**)&pl,  g_pool_lo);
    cudaGetSymbolAddress((void**)&h1h, g_h1_hi);
    cudaGetSymbolAddress((void**)&h1l, g_h1_lo);
    cudaGetSymbolAddress((void**)&h2_p,     g_h2);
    cudaGetSymbolAddress((void**)&logits_p, g_logits);
    cudaGetSymbolAddress((void**)&deltas_p, g_deltas);
    cudaGetSymbolAddress((void**)&rois_p,   g_rois);
    cudaGetSymbolAddress((void**)&clsT_p,   g_clsT);
    cudaGetSymbolAddress((void**)&regT_p,   g_regT);

    const int GEMM_SMEM = 2 * 30720;   // 61440 B -> 2 CTAs/SM
    cudaFuncSetAttribute(gemm_mma_kernel, cudaFuncAttributeMaxDynamicSharedMemorySize, GEMM_SMEM);

    const dim3 alignGrid(13, nroi);
    const int mTiles = (nroi + 127) / 128;
    const int cpBlocks = (nroi * 4 + 255) / 256;
    const int dbBlocks = (nroi + 255) / 256;
    const size_t w1hd = (size_t)1024 * K1;
    const size_t w2hd = (size_t)1024 * 1024;
    const long mslab = (long)nroi * 1024;
    const int smallGrid = (nroi + 3) / 4;

    copy_rois_kernel<<<cpBlocks, 256>>>(rois, rois_p, nroi * 4);

    // weight transforms
    {
        dim3 b(32, 8);
        wsplitT_kernel<<<dim3(K1 / 32, 1024 / 32, 3), b>>>(fc1_w, w1h, w1l, K1, 1024);
        wsplitT_kernel<<<dim3(1024 / 32, 1024 / 32, 3), b>>>(fc2_w, w2h, w2l, 1024, 1024);
        wT_kernel<<<dim3(1024 / 32, (81 + 31) / 32, 3), b>>>(cls_w, clsT_p, 1024, 81);
        wT_kernel<<<dim3(1024 / 32, 1, 3), b>>>(reg_w, regT_p, 1024, 4);
    }

    // cascade stages 0,1: refine rois
    for (int st = 0; st < 2; st++) {
        roi_align_kernel<<<alignGrid, 256>>>(P2, P3, P4, P5, H[0], H[1], H[2], H[3],
                                             rois_p, ph, pl);
        gemm_mma_kernel<<<dim3(16, mTiles, 1), 256, GEMM_SMEM>>>(
            ph, pl, w1h + (size_t)st * w1hd, w1l + (size_t)st * w1hd,
            fc1_b + st * 1024, nullptr, h1h, h1l, nroi, K1, 1, 0, 0, 0, 0);
        gemm_mma_kernel<<<dim3(16, mTiles, 1), 256, GEMM_SMEM>>>(
            h1h, h1l, w2h + (size_t)st * w2hd, w2l + (size_t)st * w2hd,
            fc2_b + st * 1024, h2_p, nullptr, nullptr, nroi, 1024, 1, 0, 0, 0, 0);
        gemm_smallT_kernel<<<dim3(smallGrid, 1), 256>>>(
            h2_p, regT_p + (size_t)st * 4 * 1024, reg_b + st * 4, deltas_p,
            nroi, 4, 0, 0, 0, 0);
        delta2bbox_kernel<<<dbBlocks, 256>>>(rois_p, deltas_p, nroi);
    }

    // final pooled (stage-2 rois) + 3-head ensemble, batched
    roi_align_kernel<<<alignGrid, 256>>>(P2, P3, P4, P5, H[0], H[1], H[2], H[3],
                                         rois_p, ph, pl);
    gemm_mma_kernel<<<dim3(48, mTiles, 1), 256, GEMM_SMEM>>>(
        ph, pl, w1h, w1l, fc1_b, nullptr, h1h, h1l, nroi, K1, 1, 0, 0, 0, 0);
    gemm_mma_kernel<<<dim3(16, mTiles, 3), 256, GEMM_SMEM>>>(
        h1h, h1l, w2h, w2l, fc2_b, h2_p, nullptr, nullptr, nroi, 1024, 1,
        mslab, (long)w2hd, 1024, mslab);
    gemm_smallT_kernel<<<dim3(smallGrid, 3), 256>>>(
        h2_p, clsT_p, cls_b, logits_p, nroi, 81,
        mslab, (long)81 * 1024, 81, (long)nroi * 81);

    softmax_avg_kernel<<<nroi, 128>>>(logits_p, out, nroi);
}

// round 16
// speedup vs baseline: 1.3881x; 1.0009x over previous
#include <cuda_runtime.h>
#include <cuda_bf16.h>
#include <math.h>
#include <stdint.h>

// ---------------------------------------------------------------------------
// Scratch (__device__ globals; no allocations allowed)
// ---------------------------------------------------------------------------
#define MAXROI 2048
#define K1MAX  12544

__device__ __nv_bfloat16 g_w1t_hi[3u * 1024u * K1MAX];
__device__ __nv_bfloat16 g_w1t_lo[3u * 1024u * K1MAX];
__device__ __nv_bfloat16 g_w2t_hi[3u * 1024u * 1024u];
__device__ __nv_bfloat16 g_w2t_lo[3u * 1024u * 1024u];
__device__ __nv_bfloat16 g_pool_hi[MAXROI * K1MAX];
__device__ __nv_bfloat16 g_pool_lo[MAXROI * K1MAX];
__device__ __nv_bfloat16 g_h1_hi[3u * MAXROI * 1024u];
__device__ __nv_bfloat16 g_h1_lo[3u * MAXROI * 1024u];
__device__ float g_h2[3u * MAXROI * 1024u];
__device__ float g_logits[3 * MAXROI * 81];
__device__ float g_deltas[MAXROI * 4];
__device__ float g_rois[MAXROI * 4];
__device__ float g_clsT[3 * 81 * 1024];
__device__ float g_regT[3 * 4 * 1024];

// ---------------------------------------------------------------------------
// PTX helpers (baseline compute_103-legal instructions only)
// ---------------------------------------------------------------------------
__device__ __forceinline__ uint32_t smem_u32(const void* p) {
    uint32_t a;
    asm("{ .reg .u64 t; cvta.to.shared.u64 t, %1; cvt.u32.u64 %0, t; }" : "=r"(a) : "l"(p));
    return a;
}

#define CP_ASYNC16(dst, src) \
    asm volatile("cp.async.cg.shared.global [%0], [%1], 16;" :: "r"(dst), "l"(src) : "memory")
#define CP_ASYNC16_Z(dst, src, sz) \
    asm volatile("cp.async.cg.shared.global [%0], [%1], 16, %2;" :: "r"(dst), "l"(src), "r"(sz) : "memory")
#define CP_COMMIT()  asm volatile("cp.async.commit_group;" ::: "memory")
#define CP_WAIT1()   asm volatile("cp.async.wait_group 1;" ::: "memory")
#define CP_WAIT0()   asm volatile("cp.async.wait_group 0;" ::: "memory")

#define LDSM_X4(r, addr) \
    asm volatile("ldmatrix.sync.aligned.m8n8.x4.shared.b16 {%0,%1,%2,%3}, [%4];" \
        : "=r"((r)[0]), "=r"((r)[1]), "=r"((r)[2]), "=r"((r)[3]) : "r"(addr))

#define MMA16816(d, a, b) \
    asm volatile("mma.sync.aligned.m16n8k16.row.col.f32.bf16.bf16.f32 " \
        "{%0,%1,%2,%3}, {%4,%5,%6,%7}, {%8,%9}, {%0,%1,%2,%3};" \
        : "+f"((d)[0]), "+f"((d)[1]), "+f"((d)[2]), "+f"((d)[3]) \
        : "r"((a)[0]), "r"((a)[1]), "r"((a)[2]), "r"((a)[3]), "r"((b)[0]), "r"((b)[1]))

// ---------------------------------------------------------------------------
// Copy rois
// ---------------------------------------------------------------------------
__global__ void copy_rois_kernel(const float* __restrict__ src, float* __restrict__ dst, int n4) {
    int i = blockIdx.x * blockDim.x + threadIdx.x;
    if (i < n4) dst[i] = src[i];
}

// ---------------------------------------------------------------------------
// Weight transpose + bf16 split:  W[K,N] fp32  ->  WT_hi/lo [N,K] bf16
// ---------------------------------------------------------------------------
__global__ void wsplitT_kernel(const float* __restrict__ W,
                               __nv_bfloat16* __restrict__ Thi,
                               __nv_bfloat16* __restrict__ Tlo, int K, int N) {
    __shared__ float t[32][33];
    const int h = blockIdx.z;
    const float* Wp = W + (size_t)h * K * N;
    __nv_bfloat16* Hp = Thi + (size_t)h * N * K;
    __nv_bfloat16* Lp = Tlo + (size_t)h * N * K;
    const int k0 = blockIdx.x * 32, n0 = blockIdx.y * 32;
    const int tx = threadIdx.x, ty = threadIdx.y;
#pragma unroll
    for (int r = 0; r < 32; r += 8)
        t[ty + r][tx] = Wp[(size_t)(k0 + ty + r) * N + n0 + tx];
    __syncthreads();
#pragma unroll
    for (int r = 0; r < 32; r += 8) {
        float v = t[tx][ty + r];
        __nv_bfloat16 hi = __float2bfloat16(v);
        float lo = v - __bfloat162float(hi);
        size_t o = (size_t)(n0 + ty + r) * K + k0 + tx;
        Hp[o] = hi;
        Lp[o] = __float2bfloat16(lo);
    }
}

// ---------------------------------------------------------------------------
// fp32 transpose for small head weights:  W[K,N] -> WT[N,K]  (N may be ragged)
// grid (K/32, ceil(N/32), heads), block (32,8)
// ---------------------------------------------------------------------------
__global__ void wT_kernel(const float* __restrict__ W, float* __restrict__ WT,
                          int K, int N) {
    __shared__ float t[32][33];
    const int h = blockIdx.z;
    const float* Wp = W + (size_t)h * K * N;
    float* Tp = WT + (size_t)h * N * K;
    const int k0 = blockIdx.x * 32, n0 = blockIdx.y * 32;
    const int tx = threadIdx.x, ty = threadIdx.y;
#pragma unroll
    for (int r = 0; r < 32; r += 8) {
        if (n0 + tx < N)
            t[ty + r][tx] = Wp[(size_t)(k0 + ty + r) * N + n0 + tx];
    }
    __syncthreads();
#pragma unroll
    for (int r = 0; r < 32; r += 8) {
        if (n0 + ty + r < N)
            Tp[(size_t)(n0 + ty + r) * K + k0 + tx] = t[tx][ty + r];
    }
}

// ---------------------------------------------------------------------------
// Pyramid ROI align -> bf16 hi/lo.  grid (13, nroi), block 256.
// Block handles 4 pooled pixels; 64 threads per pixel, float4 channel loads.
// ---------------------------------------------------------------------------
__global__ void roi_align_kernel(
    const float* __restrict__ P2, const float* __restrict__ P3,
    const float* __restrict__ P4, const float* __restrict__ P5,
    int H2, int H3, int H4, int H5,
    const float* __restrict__ rois,
    __nv_bfloat16* __restrict__ phi, __nv_bfloat16* __restrict__ plo)
{
    __shared__ int   s_lvl;
    __shared__ int   s_o[4][4];
    __shared__ float s_w[4][4];

    const int n   = blockIdx.y;
    const int tid = threadIdx.x;

    if (tid < 4) {
        const int pp = blockIdx.x * 4 + tid;
        const float y1 = rois[n * 4 + 0];
        const float x1 = rois[n * 4 + 1];
        const float y2 = rois[n * 4 + 2];
        const float x2 = rois[n * 4 + 3];
        const float hh = y2 - y1, ww = x2 - x1;

        float hwv = fmaxf(hh * ww, 1e-6f);
        float lf  = floorf(4.0f + log2f(sqrtf(hwv) / 224.0f));
        lf = fminf(fmaxf(lf, 2.0f), 5.0f);
        const int li = (int)lf - 2;
        if (tid == 0) s_lvl = li;

        if (pp < 49) {
            const int py = pp / 7, px = pp % 7;
            int H;
            float stride;
            switch (li) {
                case 0:  H = H2; stride = 4.0f;  break;
                case 1:  H = H3; stride = 8.0f;  break;
                case 2:  H = H4; stride = 16.0f; break;
                default: H = H5; stride = 32.0f; break;
            }
            const float s0 = y1 / stride, s1 = x1 / stride;
            const float s2 = y2 / stride, s3 = x2 / stride;
            const float gy = ((float)py + 0.5f) / 7.0f;
            const float gx = ((float)px + 0.5f) / 7.0f;
            const float ys = __fadd_rn(s0, __fmul_rn(gy, __fsub_rn(s2, s0)));
            const float xs = __fadd_rn(s1, __fmul_rn(gx, __fsub_rn(s3, s1)));

            const float Hm1 = (float)(H - 1);
            const float y0f = fminf(fmaxf(floorf(ys), 0.0f), Hm1);
            const float x0f = fminf(fmaxf(floorf(xs), 0.0f), Hm1);
            const int y0 = (int)y0f, x0 = (int)x0f;
            const int y1i = min(y0 + 1, H - 1);
            const int x1i = min(x0 + 1, H - 1);
            const float wy = fminf(fmaxf(ys - y0f, 0.0f), 1.0f);
            const float wx = fminf(fmaxf(xs - x0f, 0.0f), 1.0f);
            const float omwy = 1.0f - wy, omwx = 1.0f - wx;

            s_o[tid][0] = (y0  * H + x0 ) * 256;
            s_o[tid][1] = (y0  * H + x1i) * 256;
            s_o[tid][2] = (y1i * H + x0 ) * 256;
            s_o[tid][3] = (y1i * H + x1i) * 256;
            s_w[tid][0] = omwy * omwx;
            s_w[tid][1] = omwy * wx;
            s_w[tid][2] = wy * omwx;
            s_w[tid][3] = wy * wx;
        }
    }
    __syncthreads();

    const int sub = tid >> 6;               // pixel within block
    const int cg  = tid & 63;               // channel group (4 ch)
    const int pp  = blockIdx.x * 4 + sub;
    if (pp >= 49) return;

    const float* feat;
    switch (s_lvl) {
        case 0:  feat = P2; break;
        case 1:  feat = P3; break;
        case 2:  feat = P4; break;
        default: feat = P5; break;
    }

    const float4 f00 = *((const float4*)(feat + s_o[sub][0]) + cg);
    const float4 f01 = *((const float4*)(feat + s_o[sub][1]) + cg);
    const float4 f10 = *((const float4*)(feat + s_o[sub][2]) + cg);
    const float4 f11 = *((const float4*)(feat + s_o[sub][3]) + cg);
    const float w0 = s_w[sub][0], w1 = s_w[sub][1], w2 = s_w[sub][2], w3 = s_w[sub][3];

    float4 r;
    r.x = f00.x * w0 + f01.x * w1 + f10.x * w2 + f11.x * w3;
    r.y = f00.y * w0 + f01.y * w1 + f10.y * w2 + f11.y * w3;
    r.z = f00.z * w0 + f01.z * w1 + f10.z * w2 + f11.z * w3;
    r.w = f00.w * w0 + f01.w * w1 + f10.w * w2 + f11.w * w3;

    const size_t idx = ((size_t)n * 49 + pp) * 256 + cg * 4;
    __nv_bfloat16 hx = __float2bfloat16(r.x);
    __nv_bfloat16 hy = __float2bfloat16(r.y);
    __nv_bfloat16 hz = __float2bfloat16(r.z);
    __nv_bfloat16 hw = __float2bfloat16(r.w);
    phi[idx + 0] = hx;  phi[idx + 1] = hy;  phi[idx + 2] = hz;  phi[idx + 3] = hw;
    plo[idx + 0] = __float2bfloat16(r.x - __bfloat162float(hx));
    plo[idx + 1] = __float2bfloat16(r.y - __bfloat162float(hy));
    plo[idx + 2] = __float2bfloat16(r.z - __bfloat162float(hz));
    plo[idx + 3] = __float2bfloat16(r.w - __bfloat162float(hw));
}

// ---------------------------------------------------------------------------
// mma.sync split-bf16 GEMM.  Logical output width is always 1024:
//   B has NB rows (1024, or 3072 for head-batched fc1); output column colg maps
//   to (head = colg>>10, col = colg&1023) at head*M*1024 + row*1024 + col.
// D += AhiBhi + AhiBlo + AloBhi (fp32 accum, ~2^-16).
// CTA tile 128x64, BK=32, 8 warps, 2-stage cp.async, 2 CTAs/SM.
// ---------------------------------------------------------------------------
__global__ __launch_bounds__(256, 2) void gemm_mma_kernel(
    const __nv_bfloat16* __restrict__ Ahi, const __nv_bfloat16* __restrict__ Alo,
    const __nv_bfloat16* __restrict__ Bhi, const __nv_bfloat16* __restrict__ Blo,
    const float* __restrict__ bias,
    float* __restrict__ Cf, __nv_bfloat16* __restrict__ Chi, __nv_bfloat16* __restrict__ Clo,
    int M, int K, int doRelu,
    long zA, long zB, long zBias, long zC)
{
    extern __shared__ char smem[];
    const uint32_t sb = smem_u32(smem);

    const int z = blockIdx.z;
    Ahi += (size_t)zA * z;  Alo += (size_t)zA * z;
    Bhi += (size_t)zB * z;  Blo += (size_t)zB * z;
    bias += (size_t)zBias * z;
    if (Cf)  Cf  += (size_t)zC * z;
    if (Chi) { Chi += (size_t)zC * z; Clo += (size_t)zC * z; }

    const int tid  = threadIdx.x;
    const int lane = tid & 31, warp = tid >> 5;
    const int warpM = warp & 3, warpN = warp >> 2;
    const int wm0 = warpM * 32, wn0 = warpN * 32;
    const int bm0 = blockIdx.y * 128, bn0 = blockIdx.x * 64;

    const uint32_t STAGE = 30720u;   // Ahi 10240 | Alo 10240 | Bhi 5120 | Blo 5120

    float acc[2][4][4];
#pragma unroll
    for (int mt = 0; mt < 2; mt++)
#pragma unroll
        for (int nt = 0; nt < 4; nt++)
#pragma unroll
            for (int i = 0; i < 4; i++) acc[mt][nt][i] = 0.0f;

    auto load_stage = [&](int s, int kc) {
        const int k0 = kc * 32;
        const uint32_t base = sb + (uint32_t)s * STAGE;
#pragma unroll
        for (int it = 0; it < 2; it++) {
            const int i   = tid + it * 256;
            const int row = i >> 2, cj = i & 3;
            const uint32_t d  = base + (uint32_t)row * 80u + (uint32_t)cj * 16u;
            const int gr = bm0 + row;
            const int sz = (gr < M) ? 16 : 0;
            const size_t go = (size_t)gr * K + k0 + cj * 8;
            CP_ASYNC16_Z(d,           Ahi + go, sz);
            CP_ASYNC16_Z(d + 10240u,  Alo + go, sz);
        }
        {
            const int row = tid >> 2, cj = tid & 3;
            const uint32_t d = base + 20480u + (uint32_t)row * 80u + (uint32_t)cj * 16u;
            const size_t go = (size_t)(bn0 + row) * K + k0 + cj * 8;
            CP_ASYNC16(d,          Bhi + go);
            CP_ASYNC16(d + 5120u,  Blo + go);
        }
        CP_COMMIT();
    };

    const uint32_t aRow = (uint32_t)(wm0 + (lane & 15));
    const uint32_t aCol = (uint32_t)((lane >> 4) * 16);
    const uint32_t bRow = (uint32_t)(wn0 + ((lane >> 4) & 1) * 8 + (lane & 7));
    const uint32_t bCol = (uint32_t)(((lane >> 3) & 1) * 16);

    const int nkc = K >> 5;
    load_stage(0, 0);

    for (int kc = 0; kc < nkc; kc++) {
        if (kc + 1 < nkc) {
            load_stage((kc + 1) & 1, kc + 1);
            CP_WAIT1();
        } else {
            CP_WAIT0();
        }
        __syncthreads();

        const uint32_t base = sb + (uint32_t)(kc & 1) * STAGE;
#pragma unroll
        for (int ks = 0; ks < 2; ks++) {
            uint32_t a_h[2][4], a_l[2][4];
#pragma unroll
            for (int mt = 0; mt < 2; mt++) {
                const uint32_t ad = base + (aRow + (uint32_t)mt * 16u) * 80u + aCol + (uint32_t)ks * 32u;
                LDSM_X4(a_h[mt], ad);
                LDSM_X4(a_l[mt], ad + 10240u);
            }
            uint32_t b_h[4][2], b_l[4][2];
#pragma unroll
            for (int p = 0; p < 2; p++) {
                const uint32_t bd = base + 20480u + (bRow + (uint32_t)p * 16u) * 80u + bCol + (uint32_t)ks * 32u;
                uint32_t r[4];
                LDSM_X4(r, bd);
                b_h[2*p][0] = r[0]; b_h[2*p][1] = r[1];
                b_h[2*p+1][0] = r[2]; b_h[2*p+1][1] = r[3];
                LDSM_X4(r, bd + 5120u);
                b_l[2*p][0] = r[0]; b_l[2*p][1] = r[1];
                b_l[2*p+1][0] = r[2]; b_l[2*p+1][1] = r[3];
            }
#pragma unroll
            for (int mt = 0; mt < 2; mt++)
#pragma unroll
                for (int nt = 0; nt < 4; nt++) {
                    MMA16816(acc[mt][nt], a_h[mt], b_h[nt]);
                    MMA16816(acc[mt][nt], a_h[mt], b_l[nt]);
                    MMA16816(acc[mt][nt], a_l[mt], b_h[nt]);
                }
        }
        __syncthreads();
    }

    // epilogue with head-aware column mapping (logical out width 1024)
    const int erow = lane >> 2;
    const int ecol = (lane & 3) * 2;
#pragma unroll
    for (int mt = 0; mt < 2; mt++)
#pragma unroll
        for (int nt = 0; nt < 4; nt++) {
            const int colg = bn0 + wn0 + nt * 8 + ecol;
            const int head = colg >> 10;
            const int col  = colg & 1023;
            const float b0v = bias[colg], b1v = bias[colg + 1];
            const size_t hbase = (size_t)head * M * 1024;
#pragma unroll
            for (int h = 0; h < 2; h++) {
                const int row = bm0 + wm0 + mt * 16 + erow + h * 8;
                if (row >= M) continue;
                float v0 = acc[mt][nt][h * 2 + 0] + b0v;
                float v1 = acc[mt][nt][h * 2 + 1] + b1v;
                if (doRelu) { v0 = fmaxf(v0, 0.0f); v1 = fmaxf(v1, 0.0f); }
                const size_t o = hbase + (size_t)row * 1024 + col;
                if (Cf) { Cf[o] = v0; Cf[o + 1] = v1; }
                if (Chi) {
                    __nv_bfloat16 h0 = __float2bfloat16(v0);
                    __nv_bfloat16 h1 = __float2bfloat16(v1);
                    Chi[o]     = h0;
                    Chi[o + 1] = h1;
                    Clo[o]     = __float2bfloat16(v0 - __bfloat162float(h0));
                    Clo[o + 1] = __float2bfloat16(v1 - __bfloat162float(h1));
                }
            }
        }
}

// ---------------------------------------------------------------------------
// Small-N GEMM with transposed weights WT[N,K] (coalesced rows).
// Block handles 4 A-rows; warp per output column; K = 1024.
// grid (ceil(M/4), nz), block 256.
// ---------------------------------------------------------------------------
__global__ __launch_bounds__(256) void gemm_smallT_kernel(
    const float* __restrict__ A, const float* __restrict__ WT,
    const float* __restrict__ bias, float* __restrict__ C, int M, int N,
    long zA, long zW, long zBias, long zC)
{
    __shared__ float a[4][1024];
    const int z = blockIdx.y;
    A += (size_t)zA * z;  WT += (size_t)zW * z;
    bias += (size_t)zBias * z;  C += (size_t)zC * z;

    const int row0 = blockIdx.x * 4;
    const int nr = min(4, M - row0);
    const int tid = threadIdx.x, lane = tid & 31, warp = tid >> 5;

    for (int i = tid; i < nr * 1024; i += 256)
        a[i >> 10][i & 1023] = A[(size_t)(row0 + (i >> 10)) * 1024 + (i & 1023)];
    __syncthreads();

    for (int col = warp; col < N; col += 8) {
        float s0 = 0.f, s1 = 0.f, s2 = 0.f, s3 = 0.f;
        const float* wrow = WT + (size_t)col * 1024;
        for (int k = lane; k < 1024; k += 32) {
            const float w = wrow[k];
            s0 += a[0][k] * w;
            s1 += a[1][k] * w;
            s2 += a[2][k] * w;
            s3 += a[3][k] * w;
        }
#pragma unroll
        for (int off = 16; off > 0; off >>= 1) {
            s0 += __shfl_xor_sync(0xFFFFFFFFu, s0, off);
            s1 += __shfl_xor_sync(0xFFFFFFFFu, s1, off);
            s2 += __shfl_xor_sync(0xFFFFFFFFu, s2, off);
            s3 += __shfl_xor_sync(0xFFFFFFFFu, s3, off);
        }
        if (lane == 0) {
            const float bv = bias[col];
            if (nr > 0) C[(size_t)(row0 + 0) * N + col] = s0 + bv;
            if (nr > 1) C[(size_t)(row0 + 1) * N + col] = s1 + bv;
            if (nr > 2) C[(size_t)(row0 + 2) * N + col] = s2 + bv;
            if (nr > 3) C[(size_t)(row0 + 3) * N + col] = s3 + bv;
        }
    }
}

// ---------------------------------------------------------------------------
// delta2bbox (in-place)
// ---------------------------------------------------------------------------
__global__ void delta2bbox_kernel(float* __restrict__ rois,
                                  const float* __restrict__ deltas, int nroi)
{
    int n = blockIdx.x * blockDim.x + threadIdx.x;
    if (n >= nroi) return;
    const float y1 = rois[n * 4 + 0];
    const float x1 = rois[n * 4 + 1];
    const float y2 = rois[n * 4 + 2];
    const float x2 = rois[n * 4 + 3];
    const float d0 = deltas[n * 4 + 0] * 0.1f;
    const float d1 = deltas[n * 4 + 1] * 0.1f;
    const float d2 = deltas[n * 4 + 2] * 0.2f;
    const float d3 = deltas[n * 4 + 3] * 0.2f;
    float h = y2 - y1;
    float w = x2 - x1;
    const float cy = y1 + 0.5f * h + d0 * h;
    const float cx = x1 + 0.5f * w + d1 * w;
    h = h * expf(d2);
    w = w * expf(d3);
    rois[n * 4 + 0] = fminf(fmaxf(cy - 0.5f * h, 0.0f), 1024.0f);
    rois[n * 4 + 1] = fminf(fmaxf(cx - 0.5f * w, 0.0f), 1024.0f);
    rois[n * 4 + 2] = fminf(fmaxf(cy + 0.5f * h, 0.0f), 1024.0f);
    rois[n * 4 + 3] = fminf(fmaxf(cx + 0.5f * w, 0.0f), 1024.0f);
}

// ---------------------------------------------------------------------------
// 3-head softmax average
// ---------------------------------------------------------------------------
__global__ __launch_bounds__(128) void softmax_avg_kernel(
    const float* __restrict__ logits, float* __restrict__ out, int nroi)
{
    __shared__ float red[128];
    const int n = blockIdx.x;
    const int c = threadIdx.x;
    float acc = 0.0f;

    for (int h = 0; h < 3; h++) {
        float v = (c < 81) ? logits[(size_t)h * nroi * 81 + (size_t)n * 81 + c] : -3.0e38f;
        red[c] = v;
        __syncthreads();
#pragma unroll
        for (int s = 64; s > 0; s >>= 1) {
            if (c < s) red[c] = fmaxf(red[c], red[c + s]);
            __syncthreads();
        }
        const float m = red[0];
        __syncthreads();
        const float e = (c < 81) ? expf(v - m) : 0.0f;
        red[c] = e;
        __syncthreads();
#pragma unroll
        for (int s = 64; s > 0; s >>= 1) {
            if (c < s) red[c] += red[c + s];
            __syncthreads();
        }
        const float ssum = red[0];
        __syncthreads();
        acc += e / ssum;
    }
    if (c < 81) out[(size_t)n * 81 + c] = acc / 3.0f;
}

// ---------------------------------------------------------------------------
// Launcher
// ---------------------------------------------------------------------------
extern "C" void kernel_launch(void* const* d_in, const int* in_sizes, int n_in,
                              void* d_out, int out_size)
{
    const float* P2    = (const float*)d_in[0];
    const float* P3    = (const float*)d_in[1];
    const float* P4    = (const float*)d_in[2];
    const float* P5    = (const float*)d_in[3];
    const float* rois  = (const float*)d_in[4];
    const float* fc1_w = (const float*)d_in[5];
    const float* fc1_b = (const float*)d_in[6];
    const float* fc2_w = (const float*)d_in[7];
    const float* fc2_b = (const float*)d_in[8];
    const float* cls_w = (const float*)d_in[9];
    const float* cls_b = (const float*)d_in[10];
    const float* reg_w = (const float*)d_in[11];
    const float* reg_b = (const float*)d_in[12];
    float* out = (float*)d_out;

    const int nroi = in_sizes[4] / 4;
    if (nroi <= 0 || nroi > MAXROI) return;

    int H[4];
    for (int i = 0; i < 4; i++) {
        double e = (double)in_sizes[i] / 256.0;
        H[i] = (int)(sqrt(e) + 0.5);
    }
    const int K1 = in_sizes[5] / (3 * 1024);   // 12544
    if (K1 > K1MAX || (K1 & 31)) return;

    __nv_bfloat16 *w1h, *w1l, *w2h, *w2l, *ph, *pl, *h1h, *h1l;
    float *h2_p, *logits_p, *deltas_p, *rois_p, *clsT_p, *regT_p;
    cudaGetSymbolAddress((void**)&w1h, g_w1t_hi);
    cudaGetSymbolAddress((void**)&w1l, g_w1t_lo);
    cudaGetSymbolAddress((void**)&w2h, g_w2t_hi);
    cudaGetSymbolAddress((void**)&w2l, g_w2t_lo);
    cudaGetSymbolAddress((void**)&ph,  g_pool_hi);
    cudaGetSymbolAddress((void**)&pl,  g_pool_lo);
    cudaGetSymbolAddress((void**)&h1h, g_h1_hi);
    cudaGetSymbolAddress((void**)&h1l, g_h1_lo);
    cudaGetSymbolAddress((void**)&h2_p,     g_h2);
    cudaGetSymbolAddress((void**)&logits_p, g_logits);
    cudaGetSymbolAddress((void**)&deltas_p, g_deltas);
    cudaGetSymbolAddress((void**)&rois_p,   g_rois);
    cudaGetSymbolAddress((void**)&clsT_p,   g_clsT);
    cudaGetSymbolAddress((void**)&regT_p,   g_regT);

    const int GEMM_SMEM = 2 * 30720;   // 61440 B -> 2 CTAs/SM
    cudaFuncSetAttribute(gemm_mma_kernel, cudaFuncAttributeMaxDynamicSharedMemorySize, GEMM_SMEM);

    const dim3 alignGrid(13, nroi);
    const int mTiles = (nroi + 127) / 128;
    const int cpBlocks = (nroi * 4 + 255) / 256;
    const int dbBlocks = (nroi + 255) / 256;
    const size_t w1hd = (size_t)1024 * K1;
    const size_t w2hd = (size_t)1024 * 1024;
    const long mslab = (long)nroi * 1024;
    const int smallGrid = (nroi + 3) / 4;

    copy_rois_kernel<<<cpBlocks, 256>>>(rois, rois_p, nroi * 4);

    // weight transforms
    {
        dim3 b(32, 8);
        wsplitT_kernel<<<dim3(K1 / 32, 1024 / 32, 3), b>>>(fc1_w, w1h, w1l, K1, 1024);
        wsplitT_kernel<<<dim3(1024 / 32, 1024 / 32, 3), b>>>(fc2_w, w2h, w2l, 1024, 1024);
        wT_kernel<<<dim3(1024 / 32, (81 + 31) / 32, 3), b>>>(cls_w, clsT_p, 1024, 81);
        wT_kernel<<<dim3(1024 / 32, 1, 3), b>>>(reg_w, regT_p, 1024, 4);
    }

    // cascade stages 0,1: refine rois
    for (int st = 0; st < 2; st++) {
        roi_align_kernel<<<alignGrid, 256>>>(P2, P3, P4, P5, H[0], H[1], H[2], H[3],
                                             rois_p, ph, pl);
        gemm_mma_kernel<<<dim3(16, mTiles, 1), 256, GEMM_SMEM>>>(
            ph, pl, w1h + (size_t)st * w1hd, w1l + (size_t)st * w1hd,
            fc1_b + st * 1024, nullptr, h1h, h1l, nroi, K1, 1, 0, 0, 0, 0);
        gemm_mma_kernel<<<dim3(16, mTiles, 1), 256, GEMM_SMEM>>>(
            h1h, h1l, w2h + (size_t)st * w2hd, w2l + (size_t)st * w2hd,
            fc2_b + st * 1024, h2_p, nullptr, nullptr, nroi, 1024, 1, 0, 0, 0, 0);
        gemm_smallT_kernel<<<dim3(smallGrid, 1), 256>>>(
            h2_p, regT_p + (size_t)st * 4 * 1024, reg_b + st * 4, deltas_p,
            nroi, 4, 0, 0, 0, 0);
        delta2bbox_kernel<<<dbBlocks, 256>>>(rois_p, deltas_p, nroi);
    }

    // final pooled (stage-2 rois) + 3-head ensemble, batched
    roi_align_kernel<<<alignGrid, 256>>>(P2, P3, P4, P5, H[0], H[1], H[2], H[3],
                                         rois_p, ph, pl);
    gemm_mma_kernel<<<dim3(48, mTiles, 1), 256, GEMM_SMEM>>>(
        ph, pl, w1h, w1l, fc1_b, nullptr, h1h, h1l, nroi, K1, 1, 0, 0, 0, 0);
    gemm_mma_kernel<<<dim3(16, mTiles, 3), 256, GEMM_SMEM>>>(
        h1h, h1l, w2h, w2l, fc2_b, h2_p, nullptr, nullptr, nroi, 1024, 1,
        mslab, (long)w2hd, 1024, mslab);
    gemm_smallT_kernel<<<dim3(smallGrid, 3), 256>>>(
        h2_p, clsT_p, cls_b, logits_p, nroi, 81,
        mslab, (long)81 * 1024, 81, (long)nroi * 81);

    softmax_avg_kernel<<<nroi, 128>>>(logits_p, out, nroi);
}

// round 17
// speedup vs baseline: 1.3885x; 1.0003x over previous
#include <cuda_runtime.h>
#include <cuda_bf16.h>
#include <math.h>
#include <stdint.h>

// ---------------------------------------------------------------------------
// Scratch (__device__ globals; no allocations allowed)
// ---------------------------------------------------------------------------
#define MAXROI 2048
#define K1MAX  12544

__device__ __nv_bfloat16 g_w1t_hi[3u * 1024u * K1MAX];
__device__ __nv_bfloat16 g_w1t_lo[3u * 1024u * K1MAX];
__device__ __nv_bfloat16 g_w2t_hi[3u * 1024u * 1024u];
__device__ __nv_bfloat16 g_w2t_lo[3u * 1024u * 1024u];
__device__ __nv_bfloat16 g_pool_hi[MAXROI * K1MAX];
__device__ __nv_bfloat16 g_pool_lo[MAXROI * K1MAX];
__device__ __nv_bfloat16 g_h1_hi[3u * MAXROI * 1024u];
__device__ __nv_bfloat16 g_h1_lo[3u * MAXROI * 1024u];
__device__ float g_h2[3u * MAXROI * 1024u];
__device__ float g_logits[3 * MAXROI * 81];
__device__ float g_deltas[MAXROI * 4];
__device__ float g_rois[MAXROI * 4];
__device__ float g_clsT[3 * 81 * 1024];
__device__ float g_regT[3 * 4 * 1024];

// ---------------------------------------------------------------------------
// PTX helpers (baseline compute_103-legal instructions only)
// ---------------------------------------------------------------------------
__device__ __forceinline__ uint32_t smem_u32(const void* p) {
    uint32_t a;
    asm("{ .reg .u64 t; cvta.to.shared.u64 t, %1; cvt.u32.u64 %0, t; }" : "=r"(a) : "l"(p));
    return a;
}

#define CP_ASYNC16(dst, src) \
    asm volatile("cp.async.cg.shared.global [%0], [%1], 16;" :: "r"(dst), "l"(src) : "memory")
#define CP_ASYNC16_Z(dst, src, sz) \
    asm volatile("cp.async.cg.shared.global [%0], [%1], 16, %2;" :: "r"(dst), "l"(src), "r"(sz) : "memory")
#define CP_COMMIT()  asm volatile("cp.async.commit_group;" ::: "memory")
#define CP_WAIT1()   asm volatile("cp.async.wait_group 1;" ::: "memory")
#define CP_WAIT0()   asm volatile("cp.async.wait_group 0;" ::: "memory")

#define LDSM_X4(r, addr) \
    asm volatile("ldmatrix.sync.aligned.m8n8.x4.shared.b16 {%0,%1,%2,%3}, [%4];" \
        : "=r"((r)[0]), "=r"((r)[1]), "=r"((r)[2]), "=r"((r)[3]) : "r"(addr))

#define MMA16816(d, a, b) \
    asm volatile("mma.sync.aligned.m16n8k16.row.col.f32.bf16.bf16.f32 " \
        "{%0,%1,%2,%3}, {%4,%5,%6,%7}, {%8,%9}, {%0,%1,%2,%3};" \
        : "+f"((d)[0]), "+f"((d)[1]), "+f"((d)[2]), "+f"((d)[3]) \
        : "r"((a)[0]), "r"((a)[1]), "r"((a)[2]), "r"((a)[3]), "r"((b)[0]), "r"((b)[1]))

// ---------------------------------------------------------------------------
// Copy rois
// ---------------------------------------------------------------------------
__global__ void copy_rois_kernel(const float* __restrict__ src, float* __restrict__ dst, int n4) {
    int i = blockIdx.x * blockDim.x + threadIdx.x;
    if (i < n4) dst[i] = src[i];
}

// ---------------------------------------------------------------------------
// Weight transpose + bf16 split:  W[K,N] fp32  ->  WT_hi/lo [N,K] bf16
// ---------------------------------------------------------------------------
__global__ void wsplitT_kernel(const float* __restrict__ W,
                               __nv_bfloat16* __restrict__ Thi,
                               __nv_bfloat16* __restrict__ Tlo, int K, int N) {
    __shared__ float t[32][33];
    const int h = blockIdx.z;
    const float* Wp = W + (size_t)h * K * N;
    __nv_bfloat16* Hp = Thi + (size_t)h * N * K;
    __nv_bfloat16* Lp = Tlo + (size_t)h * N * K;
    const int k0 = blockIdx.x * 32, n0 = blockIdx.y * 32;
    const int tx = threadIdx.x, ty = threadIdx.y;
#pragma unroll
    for (int r = 0; r < 32; r += 8)
        t[ty + r][tx] = Wp[(size_t)(k0 + ty + r) * N + n0 + tx];
    __syncthreads();
#pragma unroll
    for (int r = 0; r < 32; r += 8) {
        float v = t[tx][ty + r];
        __nv_bfloat16 hi = __float2bfloat16(v);
        float lo = v - __bfloat162float(hi);
        size_t o = (size_t)(n0 + ty + r) * K + k0 + tx;
        Hp[o] = hi;
        Lp[o] = __float2bfloat16(lo);
    }
}

// ---------------------------------------------------------------------------
// fp32 transpose for small head weights:  W[K,N] -> WT[N,K]  (N may be ragged)
// grid (K/32, ceil(N/32), heads), block (32,8)
// ---------------------------------------------------------------------------
__global__ void wT_kernel(const float* __restrict__ W, float* __restrict__ WT,
                          int K, int N) {
    __shared__ float t[32][33];
    const int h = blockIdx.z;
    const float* Wp = W + (size_t)h * K * N;
    float* Tp = WT + (size_t)h * N * K;
    const int k0 = blockIdx.x * 32, n0 = blockIdx.y * 32;
    const int tx = threadIdx.x, ty = threadIdx.y;
#pragma unroll
    for (int r = 0; r < 32; r += 8) {
        if (n0 + tx < N)
            t[ty + r][tx] = Wp[(size_t)(k0 + ty + r) * N + n0 + tx];
    }
    __syncthreads();
#pragma unroll
    for (int r = 0; r < 32; r += 8) {
        if (n0 + ty + r < N)
            Tp[(size_t)(n0 + ty + r) * K + k0 + tx] = t[tx][ty + r];
    }
}

// ---------------------------------------------------------------------------
// Pyramid ROI align -> bf16 hi/lo.  grid (13, nroi), block 256.
// Block handles 4 pooled pixels; 64 threads per pixel, float4 channel loads.
// ---------------------------------------------------------------------------
__global__ void roi_align_kernel(
    const float* __restrict__ P2, const float* __restrict__ P3,
    const float* __restrict__ P4, const float* __restrict__ P5,
    int H2, int H3, int H4, int H5,
    const float* __restrict__ rois,
    __nv_bfloat16* __restrict__ phi, __nv_bfloat16* __restrict__ plo)
{
    __shared__ int   s_lvl;
    __shared__ int   s_o[4][4];
    __shared__ float s_w[4][4];

    const int n   = blockIdx.y;
    const int tid = threadIdx.x;

    if (tid < 4) {
        const int pp = blockIdx.x * 4 + tid;
        const float y1 = rois[n * 4 + 0];
        const float x1 = rois[n * 4 + 1];
        const float y2 = rois[n * 4 + 2];
        const float x2 = rois[n * 4 + 3];
        const float hh = y2 - y1, ww = x2 - x1;

        float hwv = fmaxf(hh * ww, 1e-6f);
        float lf  = floorf(4.0f + log2f(sqrtf(hwv) / 224.0f));
        lf = fminf(fmaxf(lf, 2.0f), 5.0f);
        const int li = (int)lf - 2;
        if (tid == 0) s_lvl = li;

        if (pp < 49) {
            const int py = pp / 7, px = pp % 7;
            int H;
            float stride;
            switch (li) {
                case 0:  H = H2; stride = 4.0f;  break;
                case 1:  H = H3; stride = 8.0f;  break;
                case 2:  H = H4; stride = 16.0f; break;
                default: H = H5; stride = 32.0f; break;
            }
            const float s0 = y1 / stride, s1 = x1 / stride;
            const float s2 = y2 / stride, s3 = x2 / stride;
            const float gy = ((float)py + 0.5f) / 7.0f;
            const float gx = ((float)px + 0.5f) / 7.0f;
            const float ys = __fadd_rn(s0, __fmul_rn(gy, __fsub_rn(s2, s0)));
            const float xs = __fadd_rn(s1, __fmul_rn(gx, __fsub_rn(s3, s1)));

            const float Hm1 = (float)(H - 1);
            const float y0f = fminf(fmaxf(floorf(ys), 0.0f), Hm1);
            const float x0f = fminf(fmaxf(floorf(xs), 0.0f), Hm1);
            const int y0 = (int)y0f, x0 = (int)x0f;
            const int y1i = min(y0 + 1, H - 1);
            const int x1i = min(x0 + 1, H - 1);
            const float wy = fminf(fmaxf(ys - y0f, 0.0f), 1.0f);
            const float wx = fminf(fmaxf(xs - x0f, 0.0f), 1.0f);
            const float omwy = 1.0f - wy, omwx = 1.0f - wx;

            s_o[tid][0] = (y0  * H + x0 ) * 256;
            s_o[tid][1] = (y0  * H + x1i) * 256;
            s_o[tid][2] = (y1i * H + x0 ) * 256;
            s_o[tid][3] = (y1i * H + x1i) * 256;
            s_w[tid][0] = omwy * omwx;
            s_w[tid][1] = omwy * wx;
            s_w[tid][2] = wy * omwx;
            s_w[tid][3] = wy * wx;
        }
    }
    __syncthreads();

    const int sub = tid >> 6;               // pixel within block
    const int cg  = tid & 63;               // channel group (4 ch)
    const int pp  = blockIdx.x * 4 + sub;
    if (pp >= 49) return;

    const float* feat;
    switch (s_lvl) {
        case 0:  feat = P2; break;
        case 1:  feat = P3; break;
        case 2:  feat = P4; break;
        default: feat = P5; break;
    }

    const float4 f00 = *((const float4*)(feat + s_o[sub][0]) + cg);
    const float4 f01 = *((const float4*)(feat + s_o[sub][1]) + cg);
    const float4 f10 = *((const float4*)(feat + s_o[sub][2]) + cg);
    const float4 f11 = *((const float4*)(feat + s_o[sub][3]) + cg);
    const float w0 = s_w[sub][0], w1 = s_w[sub][1], w2 = s_w[sub][2], w3 = s_w[sub][3];

    float4 r;
    r.x = f00.x * w0 + f01.x * w1 + f10.x * w2 + f11.x * w3;
    r.y = f00.y * w0 + f01.y * w1 + f10.y * w2 + f11.y * w3;
    r.z = f00.z * w0 + f01.z * w1 + f10.z * w2 + f11.z * w3;
    r.w = f00.w * w0 + f01.w * w1 + f10.w * w2 + f11.w * w3;

    const size_t idx = ((size_t)n * 49 + pp) * 256 + cg * 4;
    __nv_bfloat16 hx = __float2bfloat16(r.x);
    __nv_bfloat16 hy = __float2bfloat16(r.y);
    __nv_bfloat16 hz = __float2bfloat16(r.z);
    __nv_bfloat16 hw = __float2bfloat16(r.w);
    phi[idx + 0] = hx;  phi[idx + 1] = hy;  phi[idx + 2] = hz;  phi[idx + 3] = hw;
    plo[idx + 0] = __float2bfloat16(r.x - __bfloat162float(hx));
    plo[idx + 1] = __float2bfloat16(r.y - __bfloat162float(hy));
    plo[idx + 2] = __float2bfloat16(r.z - __bfloat162float(hz));
    plo[idx + 3] = __float2bfloat16(r.w - __bfloat162float(hw));
}

// ---------------------------------------------------------------------------
// mma.sync split-bf16 GEMM.  Logical output width is always 1024:
//   B has NB rows (1024, or 3072 for head-batched fc1); output column colg maps
//   to (head = colg>>10, col = colg&1023) at head*M*1024 + row*1024 + col.
// D += AhiBhi + AhiBlo + AloBhi (fp32 accum, ~2^-16).
// CTA tile 128x64, BK=32, 8 warps, 2-stage cp.async, 2 CTAs/SM.
// ---------------------------------------------------------------------------
__global__ __launch_bounds__(256, 2) void gemm_mma_kernel(
    const __nv_bfloat16* __restrict__ Ahi, const __nv_bfloat16* __restrict__ Alo,
    const __nv_bfloat16* __restrict__ Bhi, const __nv_bfloat16* __restrict__ Blo,
    const float* __restrict__ bias,
    float* __restrict__ Cf, __nv_bfloat16* __restrict__ Chi, __nv_bfloat16* __restrict__ Clo,
    int M, int K, int doRelu,
    long zA, long zB, long zBias, long zC)
{
    extern __shared__ char smem[];
    const uint32_t sb = smem_u32(smem);

    const int z = blockIdx.z;
    Ahi += (size_t)zA * z;  Alo += (size_t)zA * z;
    Bhi += (size_t)zB * z;  Blo += (size_t)zB * z;
    bias += (size_t)zBias * z;
    if (Cf)  Cf  += (size_t)zC * z;
    if (Chi) { Chi += (size_t)zC * z; Clo += (size_t)zC * z; }

    const int tid  = threadIdx.x;
    const int lane = tid & 31, warp = tid >> 5;
    const int warpM = warp & 3, warpN = warp >> 2;
    const int wm0 = warpM * 32, wn0 = warpN * 32;
    const int bm0 = blockIdx.y * 128, bn0 = blockIdx.x * 64;

    const uint32_t STAGE = 30720u;   // Ahi 10240 | Alo 10240 | Bhi 5120 | Blo 5120

    float acc[2][4][4];
#pragma unroll
    for (int mt = 0; mt < 2; mt++)
#pragma unroll
        for (int nt = 0; nt < 4; nt++)
#pragma unroll
            for (int i = 0; i < 4; i++) acc[mt][nt][i] = 0.0f;

    auto load_stage = [&](int s, int kc) {
        const int k0 = kc * 32;
        const uint32_t base = sb + (uint32_t)s * STAGE;
#pragma unroll
        for (int it = 0; it < 2; it++) {
            const int i   = tid + it * 256;
            const int row = i >> 2, cj = i & 3;
            const uint32_t d  = base + (uint32_t)row * 80u + (uint32_t)cj * 16u;
            const int gr = bm0 + row;
            const int sz = (gr < M) ? 16 : 0;
            const size_t go = (size_t)gr * K + k0 + cj * 8;
            CP_ASYNC16_Z(d,           Ahi + go, sz);
            CP_ASYNC16_Z(d + 10240u,  Alo + go, sz);
        }
        {
            const int row = tid >> 2, cj = tid & 3;
            const uint32_t d = base + 20480u + (uint32_t)row * 80u + (uint32_t)cj * 16u;
            const size_t go = (size_t)(bn0 + row) * K + k0 + cj * 8;
            CP_ASYNC16(d,          Bhi + go);
            CP_ASYNC16(d + 5120u,  Blo + go);
        }
        CP_COMMIT();
    };

    const uint32_t aRow = (uint32_t)(wm0 + (lane & 15));
    const uint32_t aCol = (uint32_t)((lane >> 4) * 16);
    const uint32_t bRow = (uint32_t)(wn0 + ((lane >> 4) & 1) * 8 + (lane & 7));
    const uint32_t bCol = (uint32_t)(((lane >> 3) & 1) * 16);

    const int nkc = K >> 5;
    load_stage(0, 0);

    for (int kc = 0; kc < nkc; kc++) {
        if (kc + 1 < nkc) {
            load_stage((kc + 1) & 1, kc + 1);
            CP_WAIT1();
        } else {
            CP_WAIT0();
        }
        __syncthreads();

        const uint32_t base = sb + (uint32_t)(kc & 1) * STAGE;
#pragma unroll
        for (int ks = 0; ks < 2; ks++) {
            uint32_t a_h[2][4], a_l[2][4];
#pragma unroll
            for (int mt = 0; mt < 2; mt++) {
                const uint32_t ad = base + (aRow + (uint32_t)mt * 16u) * 80u + aCol + (uint32_t)ks * 32u;
                LDSM_X4(a_h[mt], ad);
                LDSM_X4(a_l[mt], ad + 10240u);
            }
            uint32_t b_h[4][2], b_l[4][2];
#pragma unroll
            for (int p = 0; p < 2; p++) {
                const uint32_t bd = base + 20480u + (bRow + (uint32_t)p * 16u) * 80u + bCol + (uint32_t)ks * 32u;
                uint32_t r[4];
                LDSM_X4(r, bd);
                b_h[2*p][0] = r[0]; b_h[2*p][1] = r[1];
                b_h[2*p+1][0] = r[2]; b_h[2*p+1][1] = r[3];
                LDSM_X4(r, bd + 5120u);
                b_l[2*p][0] = r[0]; b_l[2*p][1] = r[1];
                b_l[2*p+1][0] = r[2]; b_l[2*p+1][1] = r[3];
            }
#pragma unroll
            for (int mt = 0; mt < 2; mt++)
#pragma unroll
                for (int nt = 0; nt < 4; nt++) {
                    MMA16816(acc[mt][nt], a_h[mt], b_h[nt]);
                    MMA16816(acc[mt][nt], a_h[mt], b_l[nt]);
                    MMA16816(acc[mt][nt], a_l[mt], b_h[nt]);
                }
        }
        __syncthreads();
    }

    // epilogue with head-aware column mapping (logical out width 1024)
    const int erow = lane >> 2;
    const int ecol = (lane & 3) * 2;
#pragma unroll
    for (int mt = 0; mt < 2; mt++)
#pragma unroll
        for (int nt = 0; nt < 4; nt++) {
            const int colg = bn0 + wn0 + nt * 8 + ecol;
            const int head = colg >> 10;
            const int col  = colg & 1023;
            const float b0v = bias[colg], b1v = bias[colg + 1];
            const size_t hbase = (size_t)head * M * 1024;
#pragma unroll
            for (int h = 0; h < 2; h++) {
                const int row = bm0 + wm0 + mt * 16 + erow + h * 8;
                if (row >= M) continue;
                float v0 = acc[mt][nt][h * 2 + 0] + b0v;
                float v1 = acc[mt][nt][h * 2 + 1] + b1v;
                if (doRelu) { v0 = fmaxf(v0, 0.0f); v1 = fmaxf(v1, 0.0f); }
                const size_t o = hbase + (size_t)row * 1024 + col;
                if (Cf) { Cf[o] = v0; Cf[o + 1] = v1; }
                if (Chi) {
                    __nv_bfloat16 h0 = __float2bfloat16(v0);
                    __nv_bfloat16 h1 = __float2bfloat16(v1);
                    Chi[o]     = h0;
                    Chi[o + 1] = h1;
                    Clo[o]     = __float2bfloat16(v0 - __bfloat162float(h0));
                    Clo[o + 1] = __float2bfloat16(v1 - __bfloat162float(h1));
                }
            }
        }
}

// ---------------------------------------------------------------------------
// Small-N GEMM with transposed weights WT[N,K] (coalesced rows).
// Block handles 4 A-rows; warp per output column; K = 1024.
// grid (ceil(M/4), nz), block 256.
// ---------------------------------------------------------------------------
__global__ __launch_bounds__(256) void gemm_smallT_kernel(
    const float* __restrict__ A, const float* __restrict__ WT,
    const float* __restrict__ bias, float* __restrict__ C, int M, int N,
    long zA, long zW, long zBias, long zC)
{
    __shared__ float a[4][1024];
    const int z = blockIdx.y;
    A += (size_t)zA * z;  WT += (size_t)zW * z;
    bias += (size_t)zBias * z;  C += (size_t)zC * z;

    const int row0 = blockIdx.x * 4;
    const int nr = min(4, M - row0);
    const int tid = threadIdx.x, lane = tid & 31, warp = tid >> 5;

    for (int i = tid; i < nr * 1024; i += 256)
        a[i >> 10][i & 1023] = A[(size_t)(row0 + (i >> 10)) * 1024 + (i & 1023)];
    __syncthreads();

    for (int col = warp; col < N; col += 8) {
        float s0 = 0.f, s1 = 0.f, s2 = 0.f, s3 = 0.f;
        const float* wrow = WT + (size_t)col * 1024;
        for (int k = lane; k < 1024; k += 32) {
            const float w = wrow[k];
            s0 += a[0][k] * w;
            s1 += a[1][k] * w;
            s2 += a[2][k] * w;
            s3 += a[3][k] * w;
        }
#pragma unroll
        for (int off = 16; off > 0; off >>= 1) {
            s0 += __shfl_xor_sync(0xFFFFFFFFu, s0, off);
            s1 += __shfl_xor_sync(0xFFFFFFFFu, s1, off);
            s2 += __shfl_xor_sync(0xFFFFFFFFu, s2, off);
            s3 += __shfl_xor_sync(0xFFFFFFFFu, s3, off);
        }
        if (lane == 0) {
            const float bv = bias[col];
            if (nr > 0) C[(size_t)(row0 + 0) * N + col] = s0 + bv;
            if (nr > 1) C[(size_t)(row0 + 1) * N + col] = s1 + bv;
            if (nr > 2) C[(size_t)(row0 + 2) * N + col] = s2 + bv;
            if (nr > 3) C[(size_t)(row0 + 3) * N + col] = s3 + bv;
        }
    }
}

// ---------------------------------------------------------------------------
// delta2bbox (in-place)
// ---------------------------------------------------------------------------
__global__ void delta2bbox_kernel(float* __restrict__ rois,
                                  const float* __restrict__ deltas, int nroi)
{
    int n = blockIdx.x * blockDim.x + threadIdx.x;
    if (n >= nroi) return;
    const float y1 = rois[n * 4 + 0];
    const float x1 = rois[n * 4 + 1];
    const float y2 = rois[n * 4 + 2];
    const float x2 = rois[n * 4 + 3];
    const float d0 = deltas[n * 4 + 0] * 0.1f;
    const float d1 = deltas[n * 4 + 1] * 0.1f;
    const float d2 = deltas[n * 4 + 2] * 0.2f;
    const float d3 = deltas[n * 4 + 3] * 0.2f;
    float h = y2 - y1;
    float w = x2 - x1;
    const float cy = y1 + 0.5f * h + d0 * h;
    const float cx = x1 + 0.5f * w + d1 * w;
    h = h * expf(d2);
    w = w * expf(d3);
    rois[n * 4 + 0] = fminf(fmaxf(cy - 0.5f * h, 0.0f), 1024.0f);
    rois[n * 4 + 1] = fminf(fmaxf(cx - 0.5f * w, 0.0f), 1024.0f);
    rois[n * 4 + 2] = fminf(fmaxf(cy + 0.5f * h, 0.0f), 1024.0f);
    rois[n * 4 + 3] = fminf(fmaxf(cx + 0.5f * w, 0.0f), 1024.0f);
}

// ---------------------------------------------------------------------------
// 3-head softmax average
// ---------------------------------------------------------------------------
__global__ __launch_bounds__(128) void softmax_avg_kernel(
    const float* __restrict__ logits, float* __restrict__ out, int nroi)
{
    __shared__ float red[128];
    const int n = blockIdx.x;
    const int c = threadIdx.x;
    float acc = 0.0f;

    for (int h = 0; h < 3; h++) {
        float v = (c < 81) ? logits[(size_t)h * nroi * 81 + (size_t)n * 81 + c] : -3.0e38f;
        red[c] = v;
        __syncthreads();
#pragma unroll
        for (int s = 64; s > 0; s >>= 1) {
            if (c < s) red[c] = fmaxf(red[c], red[c + s]);
            __syncthreads();
        }
        const float m = red[0];
        __syncthreads();
        const float e = (c < 81) ? expf(v - m) : 0.0f;
        red[c] = e;
        __syncthreads();
#pragma unroll
        for (int s = 64; s > 0; s >>= 1) {
            if (c < s) red[c] += red[c + s];
            __syncthreads();
        }
        const float ssum = red[0];
        __syncthreads();
        acc += e / ssum;
    }
    if (c < 81) out[(size_t)n * 81 + c] = acc / 3.0f;
}

// ---------------------------------------------------------------------------
// Launcher
// ---------------------------------------------------------------------------
extern "C" void kernel_launch(void* const* d_in, const int* in_sizes, int n_in,
                              void* d_out, int out_size)
{
    const float* P2    = (const float*)d_in[0];
    const float* P3    = (const float*)d_in[1];
    const float* P4    = (const float*)d_in[2];
    const float* P5    = (const float*)d_in[3];
    const float* rois  = (const float*)d_in[4];
    const float* fc1_w = (const float*)d_in[5];
    const float* fc1_b = (const float*)d_in[6];
    const float* fc2_w = (const float*)d_in[7];
    const float* fc2_b = (const float*)d_in[8];
    const float* cls_w = (const float*)d_in[9];
    const float* cls_b = (const float*)d_in[10];
    const float* reg_w = (const float*)d_in[11];
    const float* reg_b = (const float*)d_in[12];
    float* out = (float*)d_out;

    const int nroi = in_sizes[4] / 4;
    if (nroi <= 0 || nroi > MAXROI) return;

    int H[4];
    for (int i = 0; i < 4; i++) {
        double e = (double)in_sizes[i] / 256.0;
        H[i] = (int)(sqrt(e) + 0.5);
    }
    const int K1 = in_sizes[5] / (3 * 1024);   // 12544
    if (K1 > K1MAX || (K1 & 31)) return;

    __nv_bfloat16 *w1h, *w1l, *w2h, *w2l, *ph, *pl, *h1h, *h1l;
    float *h2_p, *logits_p, *deltas_p, *rois_p, *clsT_p, *regT_p;
    cudaGetSymbolAddress((void**)&w1h, g_w1t_hi);
    cudaGetSymbolAddress((void**)&w1l, g_w1t_lo);
    cudaGetSymbolAddress((void**)&w2h, g_w2t_hi);
    cudaGetSymbolAddress((void**)&w2l, g_w2t_lo);
    cudaGetSymbolAddress((void**)&ph,  g_pool_hi);
    cudaGetSymbolAddress((void**)&pl,  g_pool_lo);
    cudaGetSymbolAddress((void**)&h1h, g_h1_hi);
    cudaGetSymbolAddress((void**)&h1l, g_h1_lo);
    cudaGetSymbolAddress((void**)&h2_p,     g_h2);
    cudaGetSymbolAddress((void**)&logits_p, g_logits);
    cudaGetSymbolAddress((void**)&deltas_p, g_deltas);
    cudaGetSymbolAddress((void**)&rois_p,   g_rois);
    cudaGetSymbolAddress((void**)&clsT_p,   g_clsT);
    cudaGetSymbolAddress((void**)&regT_p,   g_regT);

    const int GEMM_SMEM = 2 * 30720;   // 61440 B -> 2 CTAs/SM
    cudaFuncSetAttribute(gemm_mma_kernel, cudaFuncAttributeMaxDynamicSharedMemorySize, GEMM_SMEM);

    const dim3 alignGrid(13, nroi);
    const int mTiles = (nroi + 127) / 128;
    const int cpBlocks = (nroi * 4 + 255) / 256;
    const int dbBlocks = (nroi + 255) / 256;
    const size_t w1hd = (size_t)1024 * K1;
    const size_t w2hd = (size_t)1024 * 1024;
    const long mslab = (long)nroi * 1024;
    const int smallGrid = (nroi + 3) / 4;

    copy_rois_kernel<<<cpBlocks, 256>>>(rois, rois_p, nroi * 4);

    // weight transforms
    {
        dim3 b(32, 8);
        wsplitT_kernel<<<dim3(K1 / 32, 1024 / 32, 3), b>>>(fc1_w, w1h, w1l, K1, 1024);
        wsplitT_kernel<<<dim3(1024 / 32, 1024 / 32, 3), b>>>(fc2_w, w2h, w2l, 1024, 1024);
        wT_kernel<<<dim3(1024 / 32, (81 + 31) / 32, 3), b>>>(cls_w, clsT_p, 1024, 81);
        wT_kernel<<<dim3(1024 / 32, 1, 3), b>>>(reg_w, regT_p, 1024, 4);
    }

    // cascade stages 0,1: refine rois
    for (int st = 0; st < 2; st++) {
        roi_align_kernel<<<alignGrid, 256>>>(P2, P3, P4, P5, H[0], H[1], H[2], H[3],
                                             rois_p, ph, pl);
        gemm_mma_kernel<<<dim3(16, mTiles, 1), 256, GEMM_SMEM>>>(
            ph, pl, w1h + (size_t)st * w1hd, w1l + (size_t)st * w1hd,
            fc1_b + st * 1024, nullptr, h1h, h1l, nroi, K1, 1, 0, 0, 0, 0);
        gemm_mma_kernel<<<dim3(16, mTiles, 1), 256, GEMM_SMEM>>>(
            h1h, h1l, w2h + (size_t)st * w2hd, w2l + (size_t)st * w2hd,
            fc2_b + st * 1024, h2_p, nullptr, nullptr, nroi, 1024, 1, 0, 0, 0, 0);
        gemm_smallT_kernel<<<dim3(smallGrid, 1), 256>>>(
            h2_p, regT_p + (size_t)st * 4 * 1024, reg_b + st * 4, deltas_p,
            nroi, 4, 0, 0, 0, 0);
        delta2bbox_kernel<<<dbBlocks, 256>>>(rois_p, deltas_p, nroi);
    }

    // final pooled (stage-2 rois) + 3-head ensemble, batched
    roi_align_kernel<<<alignGrid, 256>>>(P2, P3, P4, P5, H[0], H[1], H[2], H[3],
                                         rois_p, ph, pl);
    gemm_mma_kernel<<<dim3(48, mTiles, 1), 256, GEMM_SMEM>>>(
        ph, pl, w1h, w1l, fc1_b, nullptr, h1h, h1l, nroi, K1, 1, 0, 0, 0, 0);
    gemm_mma_kernel<<<dim3(16, mTiles, 3), 256, GEMM_SMEM>>>(
        h1h, h1l, w2h, w2l, fc2_b, h2_p, nullptr, nullptr, nroi, 1024, 1,
        mslab, (long)w2hd, 1024, mslab);
    gemm_smallT_kernel<<<dim3(smallGrid, 3), 256>>>(
        h2_p, clsT_p, cls_b, logits_p, nroi, 81,
        mslab, (long)81 * 1024, 81, (long)nroi * 81);

    softmax_avg_kernel<<<nroi, 128>>>(logits_p, out, nroi);
}